// round 1
// baseline (speedup 1.0000x reference)
#include <cuda_runtime.h>
#include <cuda_bf16.h>
#include <math.h>

#define NMAX 50000
#define EMAX 1600000

// ---------------- scratch (static device globals; no allocation) ----------------
__device__ float g_x[NMAX * 128];
__device__ float g_ft[NMAX * 128];
__device__ float g_el[NMAX * 8];
__device__ float g_er[NMAX * 8];
__device__ float g_m[NMAX * 8];
__device__ float g_s[NMAX * 8];
__device__ float g_acc[NMAX * 128];
__device__ float g_e[EMAX * 8];
__device__ float g_p[NMAX * 128];
__device__ float g_q[NMAX * 128];

// ---------------- helpers ----------------
__device__ __forceinline__ float atomicMaxF(float* addr, float v) {
    if (v >= 0.0f)
        return __int_as_float(atomicMax((int*)addr, __float_as_int(v)));
    else
        return __uint_as_float(atomicMin((unsigned int*)addr, __float_as_uint(v)));
}

// ---------------- GEMM: C[M,128] = A[M,128] @ W[128,128] (+bias) ----------------
// 256 threads, 64 rows per block. warp w -> rows w*8..w*8+7, lane -> cols lane*4..+3
__global__ void gemm128(const float* __restrict__ A, const float* __restrict__ W,
                        const float* __restrict__ bias, float* __restrict__ C, int M)
{
    __shared__ float As[64 * 128];   // 32KB
    __shared__ float Ws[16 * 128];   // 8KB
    int t = threadIdx.x, warp = t >> 5, lane = t & 31;
    int row0 = blockIdx.x * 64;

    float4* As4 = (float4*)As;
    const float4* A4 = (const float4*)A;
#pragma unroll
    for (int i = 0; i < 8; i++) {
        int f = t + i * 256;        // 2048 float4 total
        int r = f >> 5, c4 = f & 31;
        int gr = row0 + r;
        As4[f] = (gr < M) ? A4[gr * 32 + c4] : make_float4(0.f, 0.f, 0.f, 0.f);
    }

    float acc[8][4];
#pragma unroll
    for (int i = 0; i < 8; i++)
#pragma unroll
        for (int j = 0; j < 4; j++) acc[i][j] = 0.f;

    float4* Ws4 = (float4*)Ws;
    const float4* W4 = (const float4*)W;
    for (int kt = 0; kt < 8; kt++) {
        __syncthreads();
#pragma unroll
        for (int i = 0; i < 2; i++) {
            int f = t + i * 256;    // 512 float4 per chunk
            Ws4[f] = W4[kt * 512 + f];
        }
        __syncthreads();
#pragma unroll
        for (int kk = 0; kk < 16; kk++) {
            float4 wv = Ws4[kk * 32 + lane];
#pragma unroll
            for (int i = 0; i < 8; i++) {
                float a = As[(warp * 8 + i) * 128 + kt * 16 + kk];
                acc[i][0] += a * wv.x;
                acc[i][1] += a * wv.y;
                acc[i][2] += a * wv.z;
                acc[i][3] += a * wv.w;
            }
        }
    }

    float4 bv = make_float4(0.f, 0.f, 0.f, 0.f);
    if (bias) bv = ((const float4*)bias)[lane];
    float4* C4 = (float4*)C;
#pragma unroll
    for (int i = 0; i < 8; i++) {
        int gr = row0 + warp * 8 + i;
        if (gr < M) {
            float4 o;
            o.x = acc[i][0] + bv.x; o.y = acc[i][1] + bv.y;
            o.z = acc[i][2] + bv.z; o.w = acc[i][3] + bv.w;
            C4[gr * 32 + lane] = o;
        }
    }
}

// ---------------- per-node attention logits: el/er [N,H] ----------------
__global__ void node_attn(const float* __restrict__ ft, const float* __restrict__ al,
                          const float* __restrict__ ar, float* __restrict__ el,
                          float* __restrict__ er, int H, int Dh, int M)
{
    int n = blockIdx.x * blockDim.x + threadIdx.x;
    if (n >= M) return;
    for (int h = 0; h < H; h++) {
        float se = 0.f, sr = 0.f;
        for (int d = 0; d < Dh; d++) {
            float f = ft[n * 128 + h * Dh + d];
            se += f * al[h * Dh + d];
            sr += f * ar[h * Dh + d];
        }
        el[n * H + h] = se;
        er[n * H + h] = sr;
    }
}

// ---------------- init m=-inf, s=0, acc=0 ----------------
__global__ void init_ms(float* __restrict__ m, float* __restrict__ s,
                        float* __restrict__ acc, int nh, int nacc)
{
    int i = blockIdx.x * blockDim.x + threadIdx.x;
    if (i < nh) { m[i] = -INFINITY; s[i] = 0.f; }
    if (i < nacc) acc[i] = 0.f;
}

// ---------------- edge pass 1: e = lrelu(el[src]+er[dst]); segment max ----------------
__global__ void edge_max(const int* __restrict__ src, const int* __restrict__ dst,
                         const float* __restrict__ el, const float* __restrict__ er,
                         float* __restrict__ ebuf, float* __restrict__ m, int H, int E)
{
    int e = blockIdx.x * blockDim.x + threadIdx.x;
    if (e >= E) return;
    int s = src[e], d = dst[e];
    for (int h = 0; h < H; h++) {
        float v = el[s * H + h] + er[d * H + h];
        v = v > 0.f ? v : 0.2f * v;
        ebuf[e * H + h] = v;
        atomicMaxF(&m[d * H + h], v);
    }
}

// ---------------- edge pass 2: ex = exp(e - m[dst]); segment sum ----------------
__global__ void edge_expsum(const int* __restrict__ dst, float* __restrict__ ebuf,
                            const float* __restrict__ m, float* __restrict__ s,
                            int H, int E)
{
    int e = blockIdx.x * blockDim.x + threadIdx.x;
    if (e >= E) return;
    int d = dst[e];
    for (int h = 0; h < H; h++) {
        float ex = expf(ebuf[e * H + h] - m[d * H + h]);
        ebuf[e * H + h] = ex;
        atomicAdd(&s[d * H + h], ex);
    }
}

// ---------------- edge pass 3: acc[dst] += ft[src] * a  (warp per edge) ----------------
__global__ void edge_msg(const int* __restrict__ src, const int* __restrict__ dst,
                         const float* __restrict__ ft, const float* __restrict__ ebuf,
                         const float* __restrict__ sarr, float* __restrict__ acc,
                         int H, int logDh, int E)
{
    int gw = (blockIdx.x * blockDim.x + threadIdx.x) >> 5;
    int lane = threadIdx.x & 31;
    if (gw >= E) return;
    int s = src[gw], d = dst[gw];
    int h = (lane * 4) >> logDh;
    float a = ebuf[gw * H + h] / sarr[d * H + h];
    float4 f = ((const float4*)ft)[s * 32 + lane];
    float* dp = acc + d * 128 + lane * 4;
    asm volatile("red.global.add.v4.f32 [%0], {%1,%2,%3,%4};"
                 :: "l"(dp), "f"(f.x * a), "f"(f.y * a), "f"(f.z * a), "f"(f.w * a)
                 : "memory");
}

// ---------------- node update: x += elu(acc) ----------------
__global__ void node_update(float* __restrict__ x, const float* __restrict__ acc, int n)
{
    int i = blockIdx.x * blockDim.x + threadIdx.x;
    if (i >= n) return;
    float v = acc[i];
    v = v > 0.f ? v : expm1f(v);
    x[i] += v;
}

// ---------------- fused edge MLP ----------------
// y1 = relu(p[src]+q[dst]+b1) [128]; y2 = relu(y1@W2+b2) [64]; out = y2@W3+b3 [2]
// 128 threads (4 warps); each warp processes 4 edges per iteration.
#define MLP_WARPS 4
__global__ void edge_mlp(const int* __restrict__ src, const int* __restrict__ dst,
                         const float* __restrict__ p, const float* __restrict__ q,
                         const float* __restrict__ b1, const float* __restrict__ W2,
                         const float* __restrict__ b2, const float* __restrict__ W3,
                         const float* __restrict__ b3, float* __restrict__ out, int E)
{
    __shared__ float2 W2p[128 * 32];             // 32KB: (j, j+32) pairs
    __shared__ float y1s[MLP_WARPS][4][128];     // 8KB
    int t = threadIdx.x, lane = t & 31, warp = t >> 5;

    for (int f = t; f < 128 * 32; f += blockDim.x) {
        int k = f >> 5, j = f & 31;
        W2p[f] = make_float2(W2[k * 64 + j], W2[k * 64 + j + 32]);
    }
    __syncthreads();

    float4 b1v = ((const float4*)b1)[lane];
    float b2a = b2[lane], b2b = b2[lane + 32];
    float w3a0 = W3[lane * 2], w3a1 = W3[lane * 2 + 1];
    float w3b0 = W3[(lane + 32) * 2], w3b1 = W3[(lane + 32) * 2 + 1];
    float b30 = b3[0], b31 = b3[1];

    const float4* p4 = (const float4*)p;
    const float4* q4 = (const float4*)q;
    int ngroups = (E + 3) >> 2;

    for (int g = blockIdx.x * MLP_WARPS + warp; g < ngroups; g += gridDim.x * MLP_WARPS) {
        int ebase = g * 4;
#pragma unroll
        for (int e = 0; e < 4; e++) {
            int eid = ebase + e;
            float4 y = make_float4(0.f, 0.f, 0.f, 0.f);
            if (eid < E) {
                int s = src[eid], d = dst[eid];
                float4 pv = p4[s * 32 + lane];
                float4 qv = q4[d * 32 + lane];
                y.x = fmaxf(pv.x + qv.x + b1v.x, 0.f);
                y.y = fmaxf(pv.y + qv.y + b1v.y, 0.f);
                y.z = fmaxf(pv.z + qv.z + b1v.z, 0.f);
                y.w = fmaxf(pv.w + qv.w + b1v.w, 0.f);
            }
            *(float4*)&y1s[warp][e][lane * 4] = y;
        }
        __syncwarp();

        float a0[4], a1[4];
#pragma unroll
        for (int e = 0; e < 4; e++) { a0[e] = b2a; a1[e] = b2b; }
#pragma unroll 4
        for (int k = 0; k < 128; k++) {
            float2 w = W2p[k * 32 + lane];
#pragma unroll
            for (int e = 0; e < 4; e++) {
                float v = y1s[warp][e][k];
                a0[e] += v * w.x;
                a1[e] += v * w.y;
            }
        }

#pragma unroll
        for (int e = 0; e < 4; e++) {
            float ya = fmaxf(a0[e], 0.f), yb = fmaxf(a1[e], 0.f);
            float r0 = ya * w3a0 + yb * w3b0;
            float r1 = ya * w3a1 + yb * w3b1;
#pragma unroll
            for (int off = 16; off; off >>= 1) {
                r0 += __shfl_xor_sync(0xffffffffu, r0, off);
                r1 += __shfl_xor_sync(0xffffffffu, r1, off);
            }
            int eid = ebase + e;
            if (lane == 0 && eid < E) {
                out[eid * 2]     = r0 + b30;
                out[eid * 2 + 1] = r1 + b31;
            }
        }
        __syncwarp();
    }
}

// ---------------- host launcher ----------------
extern "C" void kernel_launch(void* const* d_in, const int* in_sizes, int n_in,
                              void* d_out, int out_size)
{
    const float* h     = (const float*)d_in[0];
    const int*   src   = (const int*)d_in[1];
    const int*   dst   = (const int*)d_in[2];
    const float* W_emb = (const float*)d_in[3];
    const float* b_emb = (const float*)d_in[4];
    const float* W_g   = (const float*)d_in[5];
    const float* al_g  = (const float*)d_in[6];
    const float* ar_g  = (const float*)d_in[7];
    const float* W_l   = (const float*)d_in[8];
    const float* al_l  = (const float*)d_in[9];
    const float* ar_l  = (const float*)d_in[10];
    const float* W1    = (const float*)d_in[11];
    const float* b1    = (const float*)d_in[12];
    const float* W2    = (const float*)d_in[13];
    const float* b2    = (const float*)d_in[14];
    const float* W3    = (const float*)d_in[15];
    const float* b3    = (const float*)d_in[16];
    float* out = (float*)d_out;

    int NN = in_sizes[0] / 128;
    int NE = in_sizes[1];

    float *x, *ft, *el, *er, *m, *s, *acc, *ebuf, *p, *q;
    cudaGetSymbolAddress((void**)&x,   g_x);
    cudaGetSymbolAddress((void**)&ft,  g_ft);
    cudaGetSymbolAddress((void**)&el,  g_el);
    cudaGetSymbolAddress((void**)&er,  g_er);
    cudaGetSymbolAddress((void**)&m,   g_m);
    cudaGetSymbolAddress((void**)&s,   g_s);
    cudaGetSymbolAddress((void**)&acc, g_acc);
    cudaGetSymbolAddress((void**)&ebuf,g_e);
    cudaGetSymbolAddress((void**)&p,   g_p);
    cudaGetSymbolAddress((void**)&q,   g_q);

    int gemm_blocks = (NN + 63) / 64;

    // embedding
    gemm128<<<gemm_blocks, 256>>>(h, W_emb, b_emb, x, NN);

    // 4 GAT layers (3 multi-head + 1 single-head)
    for (int L = 0; L < 4; L++) {
        const float* W  = (L < 3) ? (W_g + (size_t)L * 128 * 128) : W_l;
        const float* al = (L < 3) ? (al_g + (size_t)L * 128) : al_l;
        const float* ar = (L < 3) ? (ar_g + (size_t)L * 128) : ar_l;
        int H = (L < 3) ? 8 : 1;
        int Dh = 128 / H;
        int logDh = (L < 3) ? 4 : 7;

        gemm128<<<gemm_blocks, 256>>>(x, W, nullptr, ft, NN);
        node_attn<<<(NN + 127) / 128, 128>>>(ft, al, ar, el, er, H, Dh, NN);
        init_ms<<<(NN * 128 + 255) / 256, 256>>>(m, s, acc, NN * H, NN * 128);
        edge_max<<<(NE + 255) / 256, 256>>>(src, dst, el, er, ebuf, m, H, NE);
        edge_expsum<<<(NE + 255) / 256, 256>>>(dst, ebuf, m, s, H, NE);
        edge_msg<<<(NE * 32 + 255) / 256, 256>>>(src, dst, ft, ebuf, s, acc, H, logDh, NE);
        node_update<<<(NN * 128 + 255) / 256, 256>>>(x, acc, NN * 128);
    }

    // node-side halves of he@W1:  p = x@W1[0:128,:],  q = x@W1[128:256,:]
    gemm128<<<gemm_blocks, 256>>>(x, W1, nullptr, p, NN);
    gemm128<<<gemm_blocks, 256>>>(x, W1 + 128 * 128, nullptr, q, NN);

    // fused edge MLP readout
    edge_mlp<<<1184, 128>>>(src, dst, p, q, b1, W2, b2, W3, b3, out, NE);
}

// round 2
// speedup vs baseline: 2.0734x; 2.0734x over previous
#include <cuda_runtime.h>
#include <cuda_bf16.h>
#include <math.h>

#define NMAX 50000
#define EMAX 1600000

// ---------------- scratch (static device globals; no allocation) ----------------
__device__ float g_x[NMAX * 128];
__device__ float g_ft[NMAX * 128];
__device__ float g_el[NMAX * 8];
__device__ float g_er[NMAX * 8];
__device__ float g_p[NMAX * 128];
__device__ float g_q[NMAX * 128];
__device__ int   g_deg[NMAX];
__device__ int   g_cur[NMAX];
__device__ int   g_rowstart[NMAX + 1];
__device__ int   g_csrc[EMAX];

// ---------------- GEMM: C[M,128] = A[M,128] @ W[128,128] (+bias) ----------------
__global__ void gemm128(const float* __restrict__ A, const float* __restrict__ W,
                        const float* __restrict__ bias, float* __restrict__ C, int M)
{
    __shared__ float As[64 * 128];   // 32KB
    __shared__ float Ws[16 * 128];   // 8KB
    int t = threadIdx.x, warp = t >> 5, lane = t & 31;
    int row0 = blockIdx.x * 64;

    float4* As4 = (float4*)As;
    const float4* A4 = (const float4*)A;
#pragma unroll
    for (int i = 0; i < 8; i++) {
        int f = t + i * 256;
        int r = f >> 5, c4 = f & 31;
        int gr = row0 + r;
        As4[f] = (gr < M) ? A4[gr * 32 + c4] : make_float4(0.f, 0.f, 0.f, 0.f);
    }

    float acc[8][4];
#pragma unroll
    for (int i = 0; i < 8; i++)
#pragma unroll
        for (int j = 0; j < 4; j++) acc[i][j] = 0.f;

    float4* Ws4 = (float4*)Ws;
    const float4* W4 = (const float4*)W;
    for (int kt = 0; kt < 8; kt++) {
        __syncthreads();
#pragma unroll
        for (int i = 0; i < 2; i++) {
            int f = t + i * 256;
            Ws4[f] = W4[kt * 512 + f];
        }
        __syncthreads();
#pragma unroll
        for (int kk = 0; kk < 16; kk++) {
            float4 wv = Ws4[kk * 32 + lane];
#pragma unroll
            for (int i = 0; i < 8; i++) {
                float a = As[(warp * 8 + i) * 128 + kt * 16 + kk];
                acc[i][0] += a * wv.x;
                acc[i][1] += a * wv.y;
                acc[i][2] += a * wv.z;
                acc[i][3] += a * wv.w;
            }
        }
    }

    float4 bv = make_float4(0.f, 0.f, 0.f, 0.f);
    if (bias) bv = ((const float4*)bias)[lane];
    float4* C4 = (float4*)C;
#pragma unroll
    for (int i = 0; i < 8; i++) {
        int gr = row0 + warp * 8 + i;
        if (gr < M) {
            float4 o;
            o.x = acc[i][0] + bv.x; o.y = acc[i][1] + bv.y;
            o.z = acc[i][2] + bv.z; o.w = acc[i][3] + bv.w;
            C4[gr * 32 + lane] = o;
        }
    }
}

// ---------------- CSR build ----------------
__global__ void zero_int(int* __restrict__ a, int n)
{
    int i = blockIdx.x * blockDim.x + threadIdx.x;
    if (i < n) a[i] = 0;
}

__global__ void hist_dst(const int* __restrict__ dst, int* __restrict__ deg, int E)
{
    int e = blockIdx.x * blockDim.x + threadIdx.x;
    if (e < E) atomicAdd(&deg[dst[e]], 1);
}

// single block, 1024 threads: exclusive scan of deg -> rowstart (and cursor)
__global__ void scan_deg(const int* __restrict__ deg, int* __restrict__ rowstart,
                         int* __restrict__ cursor, int n)
{
    __shared__ int sums[1024];
    int t = threadIdx.x;
    int chunk = (n + 1023) / 1024;
    int beg = t * chunk;
    int end = beg + chunk < n ? beg + chunk : n;
    int s = 0;
    for (int i = beg; i < end; i++) s += deg[i];
    sums[t] = s;
    __syncthreads();
    for (int off = 1; off < 1024; off <<= 1) {
        int v = (t >= off) ? sums[t - off] : 0;
        __syncthreads();
        sums[t] += v;
        __syncthreads();
    }
    int excl = (t == 0) ? 0 : sums[t - 1];
    for (int i = beg; i < end; i++) {
        int d = deg[i];
        rowstart[i] = excl;
        cursor[i] = excl;
        excl += d;
    }
    if (t == 1023) rowstart[n] = sums[1023];
}

__global__ void scatter_csr(const int* __restrict__ src, const int* __restrict__ dst,
                            int* __restrict__ cur, int* __restrict__ csrc, int E)
{
    int e = blockIdx.x * blockDim.x + threadIdx.x;
    if (e >= E) return;
    int p = atomicAdd(&cur[dst[e]], 1);
    csrc[p] = src[e];
}

// ---------------- per-node attention logits: warp per node ----------------
__global__ void node_attn(const float* __restrict__ ft, const float* __restrict__ al,
                          const float* __restrict__ ar, float* __restrict__ el,
                          float* __restrict__ er, int H, int M)
{
    int node = (blockIdx.x * blockDim.x + threadIdx.x) >> 5;
    int lane = threadIdx.x & 31;
    if (node >= M) return;
    float4 f = ((const float4*)ft)[node * 32 + lane];
    float4 a = ((const float4*)al)[lane];
    float4 b = ((const float4*)ar)[lane];
    float pe = f.x * a.x + f.y * a.y + f.z * a.z + f.w * a.w;
    float pr = f.x * b.x + f.y * b.y + f.z * b.z + f.w * b.w;
    int glanes = 32 / H;   // lanes per head
#pragma unroll
    for (int off = 1; off < 32; off <<= 1) {
        if (off < glanes) {
            pe += __shfl_xor_sync(0xffffffffu, pe, off);
            pr += __shfl_xor_sync(0xffffffffu, pr, off);
        }
    }
    if ((lane & (glanes - 1)) == 0) {
        int h = lane / glanes;
        el[node * H + h] = pe;
        er[node * H + h] = pr;
    }
}

// ---------------- GAT aggregation: warp per node, no atomics ----------------
// softmax shift-invariance: exp(e-m)/sum == exp(e)/sum, max pass removed.
__global__ void gat_aggregate(const int* __restrict__ rowstart, const int* __restrict__ csrc,
                              const float* __restrict__ ft, const float* __restrict__ el,
                              const float* __restrict__ er, float* __restrict__ x,
                              int H, int logDh, int NN)
{
    int node = (blockIdx.x * blockDim.x + threadIdx.x) >> 5;
    int lane = threadIdx.x & 31;
    if (node >= NN) return;
    int h = (lane * 4) >> logDh;
    float erv = er[node * H + h];
    int beg = rowstart[node], end = rowstart[node + 1];

    // pass 1: softmax denominator
    float s0 = 0.f, s1 = 0.f, s2 = 0.f, s3 = 0.f;
    int p = beg;
    for (; p + 4 <= end; p += 4) {
        int n0 = csrc[p], n1 = csrc[p + 1], n2 = csrc[p + 2], n3 = csrc[p + 3];
        float e0 = el[n0 * H + h] + erv;
        float e1 = el[n1 * H + h] + erv;
        float e2 = el[n2 * H + h] + erv;
        float e3 = el[n3 * H + h] + erv;
        e0 = e0 > 0.f ? e0 : 0.2f * e0;
        e1 = e1 > 0.f ? e1 : 0.2f * e1;
        e2 = e2 > 0.f ? e2 : 0.2f * e2;
        e3 = e3 > 0.f ? e3 : 0.2f * e3;
        s0 += __expf(e0); s1 += __expf(e1); s2 += __expf(e2); s3 += __expf(e3);
    }
    for (; p < end; p++) {
        int n0 = csrc[p];
        float e0 = el[n0 * H + h] + erv;
        e0 = e0 > 0.f ? e0 : 0.2f * e0;
        s0 += __expf(e0);
    }
    float s = (s0 + s1) + (s2 + s3);
    float inv = 1.0f / s;   // deg==0 -> loops empty, acc stays 0

    // pass 2: weighted aggregation
    float4 acc = make_float4(0.f, 0.f, 0.f, 0.f);
    const float4* ft4 = (const float4*)ft;
    p = beg;
    for (; p + 2 <= end; p += 2) {
        int n0 = csrc[p], n1 = csrc[p + 1];
        float e0 = el[n0 * H + h] + erv;
        float e1 = el[n1 * H + h] + erv;
        e0 = e0 > 0.f ? e0 : 0.2f * e0;
        e1 = e1 > 0.f ? e1 : 0.2f * e1;
        float a0 = __expf(e0) * inv;
        float a1 = __expf(e1) * inv;
        float4 f0 = ft4[n0 * 32 + lane];
        float4 f1 = ft4[n1 * 32 + lane];
        acc.x += f0.x * a0 + f1.x * a1;
        acc.y += f0.y * a0 + f1.y * a1;
        acc.z += f0.z * a0 + f1.z * a1;
        acc.w += f0.w * a0 + f1.w * a1;
    }
    for (; p < end; p++) {
        int n0 = csrc[p];
        float e0 = el[n0 * H + h] + erv;
        e0 = e0 > 0.f ? e0 : 0.2f * e0;
        float a0 = __expf(e0) * inv;
        float4 f0 = ft4[n0 * 32 + lane];
        acc.x += f0.x * a0;
        acc.y += f0.y * a0;
        acc.z += f0.z * a0;
        acc.w += f0.w * a0;
    }

    // x += elu(acc), fused
    float4 xv = ((float4*)x)[node * 32 + lane];
    xv.x += acc.x > 0.f ? acc.x : expm1f(acc.x);
    xv.y += acc.y > 0.f ? acc.y : expm1f(acc.y);
    xv.z += acc.z > 0.f ? acc.z : expm1f(acc.z);
    xv.w += acc.w > 0.f ? acc.w : expm1f(acc.w);
    ((float4*)x)[node * 32 + lane] = xv;
}

// ---------------- fused edge MLP ----------------
#define MLP_WARPS 8
__global__ void edge_mlp(const int* __restrict__ src, const int* __restrict__ dst,
                         const float* __restrict__ p, const float* __restrict__ q,
                         const float* __restrict__ b1, const float* __restrict__ W2,
                         const float* __restrict__ b2, const float* __restrict__ W3,
                         const float* __restrict__ b3, float* __restrict__ out, int E)
{
    __shared__ float2 W2p[128 * 32];             // 32KB: (j, j+32) pairs
    __shared__ float y1s[MLP_WARPS][4][128];     // 16KB
    int t = threadIdx.x, lane = t & 31, warp = t >> 5;

    for (int f = t; f < 128 * 32; f += blockDim.x) {
        int k = f >> 5, j = f & 31;
        W2p[f] = make_float2(W2[k * 64 + j], W2[k * 64 + j + 32]);
    }
    __syncthreads();

    float4 b1v = ((const float4*)b1)[lane];
    float b2a = b2[lane], b2b = b2[lane + 32];
    float w3a0 = W3[lane * 2], w3a1 = W3[lane * 2 + 1];
    float w3b0 = W3[(lane + 32) * 2], w3b1 = W3[(lane + 32) * 2 + 1];
    float b30 = b3[0], b31 = b3[1];

    const float4* p4 = (const float4*)p;
    const float4* q4 = (const float4*)q;
    int ngroups = (E + 3) >> 2;

    for (int g = blockIdx.x * MLP_WARPS + warp; g < ngroups; g += gridDim.x * MLP_WARPS) {
        int ebase = g * 4;
#pragma unroll
        for (int e = 0; e < 4; e++) {
            int eid = ebase + e;
            float4 y = make_float4(0.f, 0.f, 0.f, 0.f);
            if (eid < E) {
                int s = src[eid], d = dst[eid];
                float4 pv = p4[s * 32 + lane];
                float4 qv = q4[d * 32 + lane];
                y.x = fmaxf(pv.x + qv.x + b1v.x, 0.f);
                y.y = fmaxf(pv.y + qv.y + b1v.y, 0.f);
                y.z = fmaxf(pv.z + qv.z + b1v.z, 0.f);
                y.w = fmaxf(pv.w + qv.w + b1v.w, 0.f);
            }
            *(float4*)&y1s[warp][e][lane * 4] = y;
        }
        __syncwarp();

        float a0[4], a1[4];
#pragma unroll
        for (int e = 0; e < 4; e++) { a0[e] = b2a; a1[e] = b2b; }
#pragma unroll 4
        for (int k = 0; k < 128; k++) {
            float2 w = W2p[k * 32 + lane];
#pragma unroll
            for (int e = 0; e < 4; e++) {
                float v = y1s[warp][e][k];
                a0[e] += v * w.x;
                a1[e] += v * w.y;
            }
        }

#pragma unroll
        for (int e = 0; e < 4; e++) {
            float ya = fmaxf(a0[e], 0.f), yb = fmaxf(a1[e], 0.f);
            float r0 = ya * w3a0 + yb * w3b0;
            float r1 = ya * w3a1 + yb * w3b1;
#pragma unroll
            for (int off = 16; off; off >>= 1) {
                r0 += __shfl_xor_sync(0xffffffffu, r0, off);
                r1 += __shfl_xor_sync(0xffffffffu, r1, off);
            }
            int eid = ebase + e;
            if (lane == 0 && eid < E) {
                out[eid * 2]     = r0 + b30;
                out[eid * 2 + 1] = r1 + b31;
            }
        }
        __syncwarp();
    }
}

// ---------------- host launcher ----------------
extern "C" void kernel_launch(void* const* d_in, const int* in_sizes, int n_in,
                              void* d_out, int out_size)
{
    const float* h     = (const float*)d_in[0];
    const int*   src   = (const int*)d_in[1];
    const int*   dst   = (const int*)d_in[2];
    const float* W_emb = (const float*)d_in[3];
    const float* b_emb = (const float*)d_in[4];
    const float* W_g   = (const float*)d_in[5];
    const float* al_g  = (const float*)d_in[6];
    const float* ar_g  = (const float*)d_in[7];
    const float* W_l   = (const float*)d_in[8];
    const float* al_l  = (const float*)d_in[9];
    const float* ar_l  = (const float*)d_in[10];
    const float* W1    = (const float*)d_in[11];
    const float* b1    = (const float*)d_in[12];
    const float* W2    = (const float*)d_in[13];
    const float* b2    = (const float*)d_in[14];
    const float* W3    = (const float*)d_in[15];
    const float* b3    = (const float*)d_in[16];
    float* out = (float*)d_out;

    int NN = in_sizes[0] / 128;
    int NE = in_sizes[1];

    float *x, *ft, *el, *er, *p, *q;
    int *deg, *cur, *rowstart, *csrc;
    cudaGetSymbolAddress((void**)&x,   g_x);
    cudaGetSymbolAddress((void**)&ft,  g_ft);
    cudaGetSymbolAddress((void**)&el,  g_el);
    cudaGetSymbolAddress((void**)&er,  g_er);
    cudaGetSymbolAddress((void**)&p,   g_p);
    cudaGetSymbolAddress((void**)&q,   g_q);
    cudaGetSymbolAddress((void**)&deg, g_deg);
    cudaGetSymbolAddress((void**)&cur, g_cur);
    cudaGetSymbolAddress((void**)&rowstart, g_rowstart);
    cudaGetSymbolAddress((void**)&csrc, g_csrc);

    int gemm_blocks = (NN + 63) / 64;

    // ---- CSR build (by dst) ----
    zero_int<<<(NN + 255) / 256, 256>>>(deg, NN);
    hist_dst<<<(NE + 255) / 256, 256>>>(dst, deg, NE);
    scan_deg<<<1, 1024>>>(deg, rowstart, cur, NN);
    scatter_csr<<<(NE + 255) / 256, 256>>>(src, dst, cur, csrc, NE);

    // ---- embedding ----
    gemm128<<<gemm_blocks, 256>>>(h, W_emb, b_emb, x, NN);

    // ---- 4 GAT layers ----
    for (int L = 0; L < 4; L++) {
        const float* W  = (L < 3) ? (W_g + (size_t)L * 128 * 128) : W_l;
        const float* al = (L < 3) ? (al_g + (size_t)L * 128) : al_l;
        const float* ar = (L < 3) ? (ar_g + (size_t)L * 128) : ar_l;
        int H = (L < 3) ? 8 : 1;
        int logDh = (L < 3) ? 4 : 7;

        gemm128<<<gemm_blocks, 256>>>(x, W, nullptr, ft, NN);
        node_attn<<<(NN * 32 + 255) / 256, 256>>>(ft, al, ar, el, er, H, NN);
        gat_aggregate<<<(NN * 32 + 255) / 256, 256>>>(rowstart, csrc, ft, el, er, x,
                                                      H, logDh, NN);
    }

    // ---- node-side halves of he@W1 ----
    gemm128<<<gemm_blocks, 256>>>(x, W1, nullptr, p, NN);
    gemm128<<<gemm_blocks, 256>>>(x, W1 + 128 * 128, nullptr, q, NN);

    // ---- fused edge MLP readout ----
    edge_mlp<<<608, 256>>>(src, dst, p, q, b1, W2, b2, W3, b3, out, NE);
}

// round 3
// speedup vs baseline: 3.0006x; 1.4472x over previous
#include <cuda_runtime.h>
#include <cuda_bf16.h>
#include <math.h>
#include <stdint.h>

#define NMAX 50000
#define EMAX 1600000

// ---------------- scratch (static device globals; no allocation) ----------------
__device__ float g_x[NMAX * 128];
__device__ float g_ft[NMAX * 128];
__device__ float g_el[NMAX * 8];
__device__ float g_er[NMAX * 8];
__device__ float g_p[NMAX * 128];
__device__ float g_q[NMAX * 128];
__device__ int   g_deg[NMAX];
__device__ int   g_cur[NMAX];
__device__ int   g_rowstart[NMAX + 1];
__device__ int   g_csrc[EMAX];

// ---------------- tf32 helpers ----------------
__device__ __forceinline__ uint32_t f2tf32(float f) {
    uint32_t r;
    asm("cvt.rna.tf32.f32 %0, %1;" : "=r"(r) : "f"(f));
    return r;
}

__device__ __forceinline__ void mma_tf32(float& c0, float& c1, float& c2, float& c3,
                                         uint32_t a0, uint32_t a1, uint32_t a2, uint32_t a3,
                                         uint32_t b0, uint32_t b1)
{
    asm volatile("mma.sync.aligned.m16n8k8.row.col.f32.tf32.tf32.f32 "
                 "{%0,%1,%2,%3}, {%4,%5,%6,%7}, {%8,%9}, {%0,%1,%2,%3};"
                 : "+f"(c0), "+f"(c1), "+f"(c2), "+f"(c3)
                 : "r"(a0), "r"(a1), "r"(a2), "r"(a3), "r"(b0), "r"(b1));
}

// ---------------- GEMM: C[M,128] = A[M,128] @ W[128,128] (+bias) ----------------
__global__ void gemm128(const float* __restrict__ A, const float* __restrict__ W,
                        const float* __restrict__ bias, float* __restrict__ C, int M)
{
    __shared__ float As[64 * 128];   // 32KB
    __shared__ float Ws[16 * 128];   // 8KB
    int t = threadIdx.x, warp = t >> 5, lane = t & 31;
    int row0 = blockIdx.x * 64;

    float4* As4 = (float4*)As;
    const float4* A4 = (const float4*)A;
#pragma unroll
    for (int i = 0; i < 8; i++) {
        int f = t + i * 256;
        int r = f >> 5, c4 = f & 31;
        int gr = row0 + r;
        As4[f] = (gr < M) ? A4[gr * 32 + c4] : make_float4(0.f, 0.f, 0.f, 0.f);
    }

    float acc[8][4];
#pragma unroll
    for (int i = 0; i < 8; i++)
#pragma unroll
        for (int j = 0; j < 4; j++) acc[i][j] = 0.f;

    float4* Ws4 = (float4*)Ws;
    const float4* W4 = (const float4*)W;
    for (int kt = 0; kt < 8; kt++) {
        __syncthreads();
#pragma unroll
        for (int i = 0; i < 2; i++) {
            int f = t + i * 256;
            Ws4[f] = W4[kt * 512 + f];
        }
        __syncthreads();
#pragma unroll
        for (int kk = 0; kk < 16; kk++) {
            float4 wv = Ws4[kk * 32 + lane];
#pragma unroll
            for (int i = 0; i < 8; i++) {
                float a = As[(warp * 8 + i) * 128 + kt * 16 + kk];
                acc[i][0] += a * wv.x;
                acc[i][1] += a * wv.y;
                acc[i][2] += a * wv.z;
                acc[i][3] += a * wv.w;
            }
        }
    }

    float4 bv = make_float4(0.f, 0.f, 0.f, 0.f);
    if (bias) bv = ((const float4*)bias)[lane];
    float4* C4 = (float4*)C;
#pragma unroll
    for (int i = 0; i < 8; i++) {
        int gr = row0 + warp * 8 + i;
        if (gr < M) {
            float4 o;
            o.x = acc[i][0] + bv.x; o.y = acc[i][1] + bv.y;
            o.z = acc[i][2] + bv.z; o.w = acc[i][3] + bv.w;
            C4[gr * 32 + lane] = o;
        }
    }
}

// ---------------- CSR build ----------------
__global__ void zero_int(int* __restrict__ a, int n)
{
    int i = blockIdx.x * blockDim.x + threadIdx.x;
    if (i < n) a[i] = 0;
}

__global__ void hist_dst(const int* __restrict__ dst, int* __restrict__ deg, int E)
{
    int e = blockIdx.x * blockDim.x + threadIdx.x;
    if (e < E) atomicAdd(&deg[dst[e]], 1);
}

__global__ void scan_deg(const int* __restrict__ deg, int* __restrict__ rowstart,
                         int* __restrict__ cursor, int n)
{
    __shared__ int sums[1024];
    int t = threadIdx.x;
    int chunk = (n + 1023) / 1024;
    int beg = t * chunk;
    int end = beg + chunk < n ? beg + chunk : n;
    int s = 0;
    for (int i = beg; i < end; i++) s += deg[i];
    sums[t] = s;
    __syncthreads();
    for (int off = 1; off < 1024; off <<= 1) {
        int v = (t >= off) ? sums[t - off] : 0;
        __syncthreads();
        sums[t] += v;
        __syncthreads();
    }
    int excl = (t == 0) ? 0 : sums[t - 1];
    for (int i = beg; i < end; i++) {
        int d = deg[i];
        rowstart[i] = excl;
        cursor[i] = excl;
        excl += d;
    }
    if (t == 1023) rowstart[n] = sums[1023];
}

__global__ void scatter_csr(const int* __restrict__ src, const int* __restrict__ dst,
                            int* __restrict__ cur, int* __restrict__ csrc, int E)
{
    int e = blockIdx.x * blockDim.x + threadIdx.x;
    if (e >= E) return;
    int p = atomicAdd(&cur[dst[e]], 1);
    csrc[p] = src[e];
}

// ---------------- per-node attention logits: warp per node ----------------
__global__ void node_attn(const float* __restrict__ ft, const float* __restrict__ al,
                          const float* __restrict__ ar, float* __restrict__ el,
                          float* __restrict__ er, int H, int M)
{
    int node = (blockIdx.x * blockDim.x + threadIdx.x) >> 5;
    int lane = threadIdx.x & 31;
    if (node >= M) return;
    float4 f = ((const float4*)ft)[node * 32 + lane];
    float4 a = ((const float4*)al)[lane];
    float4 b = ((const float4*)ar)[lane];
    float pe = f.x * a.x + f.y * a.y + f.z * a.z + f.w * a.w;
    float pr = f.x * b.x + f.y * b.y + f.z * b.z + f.w * b.w;
    int glanes = 32 / H;
#pragma unroll
    for (int off = 1; off < 32; off <<= 1) {
        if (off < glanes) {
            pe += __shfl_xor_sync(0xffffffffu, pe, off);
            pr += __shfl_xor_sync(0xffffffffu, pr, off);
        }
    }
    if ((lane & (glanes - 1)) == 0) {
        int h = lane / glanes;
        el[node * H + h] = pe;
        er[node * H + h] = pr;
    }
}

// ---------------- GAT aggregation: warp per node, no atomics ----------------
__global__ void gat_aggregate(const int* __restrict__ rowstart, const int* __restrict__ csrc,
                              const float* __restrict__ ft, const float* __restrict__ el,
                              const float* __restrict__ er, float* __restrict__ x,
                              int H, int logDh, int NN)
{
    int node = (blockIdx.x * blockDim.x + threadIdx.x) >> 5;
    int lane = threadIdx.x & 31;
    if (node >= NN) return;
    int h = (lane * 4) >> logDh;
    float erv = er[node * H + h];
    int beg = rowstart[node], end = rowstart[node + 1];

    float s0 = 0.f, s1 = 0.f, s2 = 0.f, s3 = 0.f;
    int p = beg;
    for (; p + 4 <= end; p += 4) {
        int n0 = csrc[p], n1 = csrc[p + 1], n2 = csrc[p + 2], n3 = csrc[p + 3];
        float e0 = el[n0 * H + h] + erv;
        float e1 = el[n1 * H + h] + erv;
        float e2 = el[n2 * H + h] + erv;
        float e3 = el[n3 * H + h] + erv;
        e0 = e0 > 0.f ? e0 : 0.2f * e0;
        e1 = e1 > 0.f ? e1 : 0.2f * e1;
        e2 = e2 > 0.f ? e2 : 0.2f * e2;
        e3 = e3 > 0.f ? e3 : 0.2f * e3;
        s0 += __expf(e0); s1 += __expf(e1); s2 += __expf(e2); s3 += __expf(e3);
    }
    for (; p < end; p++) {
        int n0 = csrc[p];
        float e0 = el[n0 * H + h] + erv;
        e0 = e0 > 0.f ? e0 : 0.2f * e0;
        s0 += __expf(e0);
    }
    float s = (s0 + s1) + (s2 + s3);
    float inv = 1.0f / s;

    float4 acc = make_float4(0.f, 0.f, 0.f, 0.f);
    const float4* ft4 = (const float4*)ft;
    p = beg;
    for (; p + 2 <= end; p += 2) {
        int n0 = csrc[p], n1 = csrc[p + 1];
        float e0 = el[n0 * H + h] + erv;
        float e1 = el[n1 * H + h] + erv;
        e0 = e0 > 0.f ? e0 : 0.2f * e0;
        e1 = e1 > 0.f ? e1 : 0.2f * e1;
        float a0 = __expf(e0) * inv;
        float a1 = __expf(e1) * inv;
        float4 f0 = ft4[n0 * 32 + lane];
        float4 f1 = ft4[n1 * 32 + lane];
        acc.x += f0.x * a0 + f1.x * a1;
        acc.y += f0.y * a0 + f1.y * a1;
        acc.z += f0.z * a0 + f1.z * a1;
        acc.w += f0.w * a0 + f1.w * a1;
    }
    for (; p < end; p++) {
        int n0 = csrc[p];
        float e0 = el[n0 * H + h] + erv;
        e0 = e0 > 0.f ? e0 : 0.2f * e0;
        float a0 = __expf(e0) * inv;
        float4 f0 = ft4[n0 * 32 + lane];
        acc.x += f0.x * a0;
        acc.y += f0.y * a0;
        acc.z += f0.z * a0;
        acc.w += f0.w * a0;
    }

    float4 xv = ((float4*)x)[node * 32 + lane];
    xv.x += acc.x > 0.f ? acc.x : expm1f(acc.x);
    xv.y += acc.y > 0.f ? acc.y : expm1f(acc.y);
    xv.z += acc.z > 0.f ? acc.z : expm1f(acc.z);
    xv.w += acc.w > 0.f ? acc.w : expm1f(acc.w);
    ((float4*)x)[node * 32 + lane] = xv;
}

// ---------------- fused edge MLP (tf32 tensor cores) ----------------
// 256 threads / 8 warps, 64 edges per tile iteration.
// y1 tile [64][132] (tf32) in dyn smem; W2 pre-packed into B fragments in dyn smem.
// warp w: m-tile (w&3), n-half (w>>2).
#define Y1_LD 132
__global__ void edge_mlp_tc(const int* __restrict__ src, const int* __restrict__ dst,
                            const float* __restrict__ p, const float* __restrict__ q,
                            const float* __restrict__ b1, const float* __restrict__ W2,
                            const float* __restrict__ b2, const float* __restrict__ W3,
                            const float* __restrict__ b3, float* __restrict__ out,
                            int E, int ntiles)
{
    extern __shared__ float dsm[];
    float*  y1s   = dsm;                         // 64*132 floats
    float2* Bfrag = (float2*)(dsm + 64 * Y1_LD); // [16 kt][8 nt][32 lane]

    __shared__ float outs[64][2][2];             // [edge][ch][nhalf]

    int t = threadIdx.x, lane = t & 31, warp = t >> 5;
    int tc = lane & 3, gr = lane >> 2;
    int mtile = warp & 3, nhalf = warp >> 2;

    // ---- pack W2 into fragment order (once per block) ----
    for (int i = t; i < 16 * 8 * 32; i += 256) {
        int ln = i & 31, nt = (i >> 5) & 7, kt = i >> 8;
        int ltc = ln & 3, lgr = ln >> 2;
        float w0 = W2[(kt * 8 + ltc) * 64 + nt * 8 + lgr];
        float w1 = W2[(kt * 8 + ltc + 4) * 64 + nt * 8 + lgr];
        Bfrag[i] = make_float2(__uint_as_float(f2tf32(w0)), __uint_as_float(f2tf32(w1)));
    }

    // ---- per-thread constants ----
    float4 b1v = ((const float4*)b1)[lane];
    // bias b2 for this thread's output columns (cols: nhalf*32 + nt*8 + 2*tc + {0,1})
    float bc0[4], bc1[4];
    float w3r[4][2][2];  // [nt][colpair j][ch]
#pragma unroll
    for (int nt = 0; nt < 4; nt++) {
        int col = nhalf * 32 + nt * 8 + tc * 2;
        bc0[nt] = b2[col];
        bc1[nt] = b2[col + 1];
        w3r[nt][0][0] = W3[col * 2];       w3r[nt][0][1] = W3[col * 2 + 1];
        w3r[nt][1][0] = W3[(col + 1) * 2]; w3r[nt][1][1] = W3[(col + 1) * 2 + 1];
    }
    float b30 = b3[0], b31 = b3[1];

    const float4* p4 = (const float4*)p;
    const float4* q4 = (const float4*)q;

    __syncthreads();

    for (int tile = blockIdx.x; tile < ntiles; tile += gridDim.x) {
        int ebase = tile * 64;

        // ---- build y1 tile: warp w handles rows w*8 .. w*8+7 ----
#pragma unroll
        for (int i = 0; i < 8; i++) {
            int row = warp * 8 + i;
            int eid = ebase + row;
            float4 y = make_float4(0.f, 0.f, 0.f, 0.f);
            if (eid < E) {
                int s = __ldg(&src[eid]), d = __ldg(&dst[eid]);
                float4 pv = p4[s * 32 + lane];
                float4 qv = q4[d * 32 + lane];
                y.x = fmaxf(pv.x + qv.x + b1v.x, 0.f);
                y.y = fmaxf(pv.y + qv.y + b1v.y, 0.f);
                y.z = fmaxf(pv.z + qv.z + b1v.z, 0.f);
                y.w = fmaxf(pv.w + qv.w + b1v.w, 0.f);
            }
            float4 yt;
            yt.x = __uint_as_float(f2tf32(y.x));
            yt.y = __uint_as_float(f2tf32(y.y));
            yt.z = __uint_as_float(f2tf32(y.z));
            yt.w = __uint_as_float(f2tf32(y.w));
            *(float4*)&y1s[row * Y1_LD + lane * 4] = yt;
        }
        __syncthreads();

        // ---- GEMM: C[16 x 32] per warp, accumulators seeded with b2 ----
        float c[4][4];
#pragma unroll
        for (int nt = 0; nt < 4; nt++) {
            c[nt][0] = bc0[nt]; c[nt][1] = bc1[nt];
            c[nt][2] = bc0[nt]; c[nt][3] = bc1[nt];
        }
        int m0 = mtile * 16;
        const float* Ar0 = y1s + (m0 + gr) * Y1_LD;
        const float* Ar1 = y1s + (m0 + gr + 8) * Y1_LD;
#pragma unroll
        for (int kt = 0; kt < 16; kt++) {
            int k0 = kt * 8;
            uint32_t a0 = __float_as_uint(Ar0[k0 + tc]);
            uint32_t a1 = __float_as_uint(Ar1[k0 + tc]);
            uint32_t a2 = __float_as_uint(Ar0[k0 + tc + 4]);
            uint32_t a3 = __float_as_uint(Ar1[k0 + tc + 4]);
            const float2* bk = Bfrag + (kt * 8 + nhalf * 4) * 32 + lane;
#pragma unroll
            for (int nt = 0; nt < 4; nt++) {
                float2 b = bk[nt * 32];
                mma_tf32(c[nt][0], c[nt][1], c[nt][2], c[nt][3],
                         a0, a1, a2, a3,
                         __float_as_uint(b.x), __float_as_uint(b.y));
            }
        }

        // ---- epilogue: relu(y2) @ W3, reduce over tc lanes ----
        float pr00 = 0.f, pr01 = 0.f, pr10 = 0.f, pr11 = 0.f;
#pragma unroll
        for (int nt = 0; nt < 4; nt++) {
            float v0 = fmaxf(c[nt][0], 0.f);
            float v1 = fmaxf(c[nt][1], 0.f);
            float v2 = fmaxf(c[nt][2], 0.f);
            float v3 = fmaxf(c[nt][3], 0.f);
            pr00 += v0 * w3r[nt][0][0] + v1 * w3r[nt][1][0];
            pr01 += v0 * w3r[nt][0][1] + v1 * w3r[nt][1][1];
            pr10 += v2 * w3r[nt][0][0] + v3 * w3r[nt][1][0];
            pr11 += v2 * w3r[nt][0][1] + v3 * w3r[nt][1][1];
        }
#pragma unroll
        for (int off = 1; off <= 2; off <<= 1) {
            pr00 += __shfl_xor_sync(0xffffffffu, pr00, off);
            pr01 += __shfl_xor_sync(0xffffffffu, pr01, off);
            pr10 += __shfl_xor_sync(0xffffffffu, pr10, off);
            pr11 += __shfl_xor_sync(0xffffffffu, pr11, off);
        }
        if (tc == 0) {
            outs[m0 + gr][0][nhalf] = pr00;
            outs[m0 + gr][1][nhalf] = pr01;
            outs[m0 + gr + 8][0][nhalf] = pr10;
            outs[m0 + gr + 8][1][nhalf] = pr11;
        }
        __syncthreads();

        if (t < 128) {
            int e = t >> 1, ch = t & 1;
            int eid = ebase + e;
            if (eid < E)
                out[eid * 2 + ch] = outs[e][ch][0] + outs[e][ch][1] + (ch ? b31 : b30);
        }
        __syncthreads();
    }
}

// ---------------- host launcher ----------------
extern "C" void kernel_launch(void* const* d_in, const int* in_sizes, int n_in,
                              void* d_out, int out_size)
{
    const float* h     = (const float*)d_in[0];
    const int*   src   = (const int*)d_in[1];
    const int*   dst   = (const int*)d_in[2];
    const float* W_emb = (const float*)d_in[3];
    const float* b_emb = (const float*)d_in[4];
    const float* W_g   = (const float*)d_in[5];
    const float* al_g  = (const float*)d_in[6];
    const float* ar_g  = (const float*)d_in[7];
    const float* W_l   = (const float*)d_in[8];
    const float* al_l  = (const float*)d_in[9];
    const float* ar_l  = (const float*)d_in[10];
    const float* W1    = (const float*)d_in[11];
    const float* b1    = (const float*)d_in[12];
    const float* W2    = (const float*)d_in[13];
    const float* b2    = (const float*)d_in[14];
    const float* W3    = (const float*)d_in[15];
    const float* b3    = (const float*)d_in[16];
    float* out = (float*)d_out;

    int NN = in_sizes[0] / 128;
    int NE = in_sizes[1];

    float *x, *ft, *el, *er, *p, *q;
    int *deg, *cur, *rowstart, *csrc;
    cudaGetSymbolAddress((void**)&x,   g_x);
    cudaGetSymbolAddress((void**)&ft,  g_ft);
    cudaGetSymbolAddress((void**)&el,  g_el);
    cudaGetSymbolAddress((void**)&er,  g_er);
    cudaGetSymbolAddress((void**)&p,   g_p);
    cudaGetSymbolAddress((void**)&q,   g_q);
    cudaGetSymbolAddress((void**)&deg, g_deg);
    cudaGetSymbolAddress((void**)&cur, g_cur);
    cudaGetSymbolAddress((void**)&rowstart, g_rowstart);
    cudaGetSymbolAddress((void**)&csrc, g_csrc);

    int gemm_blocks = (NN + 63) / 64;

    // ---- CSR build (by dst) ----
    zero_int<<<(NN + 255) / 256, 256>>>(deg, NN);
    hist_dst<<<(NE + 255) / 256, 256>>>(dst, deg, NE);
    scan_deg<<<1, 1024>>>(deg, rowstart, cur, NN);
    scatter_csr<<<(NE + 255) / 256, 256>>>(src, dst, cur, csrc, NE);

    // ---- embedding ----
    gemm128<<<gemm_blocks, 256>>>(h, W_emb, b_emb, x, NN);

    // ---- 4 GAT layers ----
    for (int L = 0; L < 4; L++) {
        const float* W  = (L < 3) ? (W_g + (size_t)L * 128 * 128) : W_l;
        const float* al = (L < 3) ? (al_g + (size_t)L * 128) : al_l;
        const float* ar = (L < 3) ? (ar_g + (size_t)L * 128) : ar_l;
        int H = (L < 3) ? 8 : 1;
        int logDh = (L < 3) ? 4 : 7;

        gemm128<<<gemm_blocks, 256>>>(x, W, nullptr, ft, NN);
        node_attn<<<(NN * 32 + 255) / 256, 256>>>(ft, al, ar, el, er, H, NN);
        gat_aggregate<<<(NN * 32 + 255) / 256, 256>>>(rowstart, csrc, ft, el, er, x,
                                                      H, logDh, NN);
    }

    // ---- node-side halves of he@W1 ----
    gemm128<<<gemm_blocks, 256>>>(x, W1, nullptr, p, NN);
    gemm128<<<gemm_blocks, 256>>>(x, W1 + 128 * 128, nullptr, q, NN);

    // ---- fused edge MLP readout (tf32 tensor cores) ----
    int ntiles = (NE + 63) / 64;
    size_t smem = 64 * Y1_LD * sizeof(float) + 16 * 8 * 32 * sizeof(float2);
    cudaFuncSetAttribute(edge_mlp_tc, cudaFuncAttributeMaxDynamicSharedMemorySize,
                         (int)smem);
    edge_mlp_tc<<<888, 256, smem>>>(src, dst, p, q, b1, W2, b2, W3, b3, out, NE, ntiles);
}

// round 4
// speedup vs baseline: 3.1370x; 1.0455x over previous
#include <cuda_runtime.h>
#include <cuda_bf16.h>
#include <cuda_fp16.h>
#include <math.h>
#include <stdint.h>

#define NMAX 50000
#define EMAX 1600000

// ---------------- scratch (static device globals; no allocation) ----------------
__device__ float g_x[NMAX * 128];
__device__ float g_ft[NMAX * 128];
__device__ float g_el[NMAX * 8];
__device__ float g_er[NMAX * 8];
__device__ __half g_p[NMAX * 128];
__device__ __half g_q[NMAX * 128];
__device__ int   g_deg[NMAX];
__device__ int   g_cur[NMAX];
__device__ int   g_rowstart[NMAX + 1];
__device__ int   g_csrc[EMAX];
__device__ float4 g_wpack[7 * 16 * 16 * 32];   // 7 matrices of packed tf32 hi/lo B-frags

// ---------------- tf32 helpers ----------------
__device__ __forceinline__ uint32_t f2tf32(float f) {
    uint32_t r;
    asm("cvt.rna.tf32.f32 %0, %1;" : "=r"(r) : "f"(f));
    return r;
}

__device__ __forceinline__ void mma_tf32(float& c0, float& c1, float& c2, float& c3,
                                         uint32_t a0, uint32_t a1, uint32_t a2, uint32_t a3,
                                         uint32_t b0, uint32_t b1)
{
    asm volatile("mma.sync.aligned.m16n8k8.row.col.f32.tf32.tf32.f32 "
                 "{%0,%1,%2,%3}, {%4,%5,%6,%7}, {%8,%9}, {%0,%1,%2,%3};"
                 : "+f"(c0), "+f"(c1), "+f"(c2), "+f"(c3)
                 : "r"(a0), "r"(a1), "r"(a2), "r"(a3), "r"(b0), "r"(b1));
}

// ---------------- pack W[128,128] into hi/lo tf32 B fragments ----------------
// out[i], i = (kt*16+nt)*32+lane: (hi(b0), hi(b1), lo(b0), lo(b1))
// b0 = W[kt*8+tc][nt*8+gr], b1 = W[kt*8+tc+4][nt*8+gr]
__global__ void pack_w(const float* __restrict__ W, float4* __restrict__ out)
{
    int i = blockIdx.x * 256 + threadIdx.x;          // 8192 total
    int lane = i & 31, nt = (i >> 5) & 15, kt = i >> 9;
    int tc = lane & 3, gr = lane >> 2;
    float w0 = W[(kt * 8 + tc) * 128 + nt * 8 + gr];
    float w1 = W[(kt * 8 + tc + 4) * 128 + nt * 8 + gr];
    uint32_t h0 = f2tf32(w0), h1 = f2tf32(w1);
    float l0f = w0 - __uint_as_float(h0);
    float l1f = w1 - __uint_as_float(h1);
    float4 o;
    o.x = __uint_as_float(h0);
    o.y = __uint_as_float(h1);
    o.z = __uint_as_float(f2tf32(l0f));
    o.w = __uint_as_float(f2tf32(l1f));
    out[i] = o;
}

// ---------------- 3xtf32 GEMM: C[M,128] = A[M,128] @ W (packed) (+bias) ----------------
// 128 threads / 4 warps, 64 rows per block. mode 0: fp32 out; mode 1: fp16 out.
__global__ __launch_bounds__(128, 4)
void gemm_tc(const float* __restrict__ A, const float4* __restrict__ Bp,
             const float* __restrict__ bias, float* __restrict__ Cf,
             __half* __restrict__ Ch, int M, int mode)
{
    __shared__ float As[64 * 132];
    int t = threadIdx.x, lane = t & 31, warp = t >> 5;
    int tc = lane & 3, gr = lane >> 2;
    int row0 = blockIdx.x * 64;

    const float4* A4 = (const float4*)A;
#pragma unroll
    for (int i = 0; i < 16; i++) {
        int f = t + i * 128;
        int r = f >> 5, c4 = f & 31;
        int grow = row0 + r;
        float4 v = (grow < M) ? A4[grow * 32 + c4] : make_float4(0.f, 0.f, 0.f, 0.f);
        *(float4*)&As[r * 132 + c4 * 4] = v;
    }
    __syncthreads();

    float c[16][4];
#pragma unroll
    for (int nt = 0; nt < 16; nt++)
#pragma unroll
        for (int j = 0; j < 4; j++) c[nt][j] = 0.f;

    int m0 = warp * 16;
    const float* Ar0 = As + (m0 + gr) * 132;
    const float* Ar1 = Ar0 + 8 * 132;

#pragma unroll
    for (int kt = 0; kt < 16; kt++) {
        int k0 = kt * 8;
        float a0 = Ar0[k0 + tc], a1 = Ar1[k0 + tc];
        float a2 = Ar0[k0 + tc + 4], a3 = Ar1[k0 + tc + 4];
        uint32_t h0 = f2tf32(a0), h1 = f2tf32(a1), h2 = f2tf32(a2), h3 = f2tf32(a3);
        uint32_t l0 = f2tf32(a0 - __uint_as_float(h0));
        uint32_t l1 = f2tf32(a1 - __uint_as_float(h1));
        uint32_t l2 = f2tf32(a2 - __uint_as_float(h2));
        uint32_t l3 = f2tf32(a3 - __uint_as_float(h3));
        const float4* bp = Bp + kt * 16 * 32 + lane;
#pragma unroll
        for (int nt = 0; nt < 16; nt++) {
            float4 b = __ldg(bp + nt * 32);
            uint32_t bh0 = __float_as_uint(b.x), bh1 = __float_as_uint(b.y);
            uint32_t bl0 = __float_as_uint(b.z), bl1 = __float_as_uint(b.w);
            // lo terms first, hi*hi last
            mma_tf32(c[nt][0], c[nt][1], c[nt][2], c[nt][3], l0, l1, l2, l3, bh0, bh1);
            mma_tf32(c[nt][0], c[nt][1], c[nt][2], c[nt][3], h0, h1, h2, h3, bl0, bl1);
            mma_tf32(c[nt][0], c[nt][1], c[nt][2], c[nt][3], h0, h1, h2, h3, bh0, bh1);
        }
    }

    // epilogue
    int r0 = row0 + m0 + gr;
    int r1 = r0 + 8;
#pragma unroll
    for (int nt = 0; nt < 16; nt++) {
        int col = nt * 8 + tc * 2;
        float b0 = 0.f, b1 = 0.f;
        if (bias) { b0 = __ldg(&bias[col]); b1 = __ldg(&bias[col + 1]); }
        float v00 = c[nt][0] + b0, v01 = c[nt][1] + b1;
        float v10 = c[nt][2] + b0, v11 = c[nt][3] + b1;
        if (mode == 0) {
            if (r0 < M) *(float2*)&Cf[r0 * 128 + col] = make_float2(v00, v01);
            if (r1 < M) *(float2*)&Cf[r1 * 128 + col] = make_float2(v10, v11);
        } else {
            if (r0 < M) ((__half2*)Ch)[r0 * 64 + nt * 4 + tc] = __floats2half2_rn(v00, v01);
            if (r1 < M) ((__half2*)Ch)[r1 * 64 + nt * 4 + tc] = __floats2half2_rn(v10, v11);
        }
    }
}

// ---------------- CSR build ----------------
__global__ void zero_int(int* __restrict__ a, int n)
{
    int i = blockIdx.x * blockDim.x + threadIdx.x;
    if (i < n) a[i] = 0;
}

__global__ void hist_dst(const int* __restrict__ dst, int* __restrict__ deg, int E)
{
    int e = blockIdx.x * blockDim.x + threadIdx.x;
    if (e < E) atomicAdd(&deg[dst[e]], 1);
}

__global__ void scan_deg(const int* __restrict__ deg, int* __restrict__ rowstart,
                         int* __restrict__ cursor, int n)
{
    __shared__ int sums[1024];
    int t = threadIdx.x;
    int chunk = (n + 1023) / 1024;
    int beg = t * chunk;
    int end = beg + chunk < n ? beg + chunk : n;
    int s = 0;
    for (int i = beg; i < end; i++) s += deg[i];
    sums[t] = s;
    __syncthreads();
    for (int off = 1; off < 1024; off <<= 1) {
        int v = (t >= off) ? sums[t - off] : 0;
        __syncthreads();
        sums[t] += v;
        __syncthreads();
    }
    int excl = (t == 0) ? 0 : sums[t - 1];
    for (int i = beg; i < end; i++) {
        int d = deg[i];
        rowstart[i] = excl;
        cursor[i] = excl;
        excl += d;
    }
    if (t == 1023) rowstart[n] = sums[1023];
}

__global__ void scatter_csr(const int* __restrict__ src, const int* __restrict__ dst,
                            int* __restrict__ cur, int* __restrict__ csrc, int E)
{
    int e = blockIdx.x * blockDim.x + threadIdx.x;
    if (e >= E) return;
    int p = atomicAdd(&cur[dst[e]], 1);
    csrc[p] = src[e];
}

// ---------------- per-node attention logits: warp per node ----------------
__global__ void node_attn(const float* __restrict__ ft, const float* __restrict__ al,
                          const float* __restrict__ ar, float* __restrict__ el,
                          float* __restrict__ er, int H, int M)
{
    int node = (blockIdx.x * blockDim.x + threadIdx.x) >> 5;
    int lane = threadIdx.x & 31;
    if (node >= M) return;
    float4 f = ((const float4*)ft)[node * 32 + lane];
    float4 a = ((const float4*)al)[lane];
    float4 b = ((const float4*)ar)[lane];
    float pe = f.x * a.x + f.y * a.y + f.z * a.z + f.w * a.w;
    float pr = f.x * b.x + f.y * b.y + f.z * b.z + f.w * b.w;
    int glanes = 32 / H;
#pragma unroll
    for (int off = 1; off < 32; off <<= 1) {
        if (off < glanes) {
            pe += __shfl_xor_sync(0xffffffffu, pe, off);
            pr += __shfl_xor_sync(0xffffffffu, pr, off);
        }
    }
    if ((lane & (glanes - 1)) == 0) {
        int h = lane / glanes;
        el[node * H + h] = pe;
        er[node * H + h] = pr;
    }
}

// ---------------- GAT aggregation: warp per node, no atomics ----------------
__global__ void gat_aggregate(const int* __restrict__ rowstart, const int* __restrict__ csrc,
                              const float* __restrict__ ft, const float* __restrict__ el,
                              const float* __restrict__ er, float* __restrict__ x,
                              int H, int logDh, int NN)
{
    int node = (blockIdx.x * blockDim.x + threadIdx.x) >> 5;
    int lane = threadIdx.x & 31;
    if (node >= NN) return;
    int h = (lane * 4) >> logDh;
    float erv = er[node * H + h];
    int beg = rowstart[node], end = rowstart[node + 1];

    float s0 = 0.f, s1 = 0.f, s2 = 0.f, s3 = 0.f;
    int p = beg;
    for (; p + 4 <= end; p += 4) {
        int n0 = csrc[p], n1 = csrc[p + 1], n2 = csrc[p + 2], n3 = csrc[p + 3];
        float e0 = el[n0 * H + h] + erv;
        float e1 = el[n1 * H + h] + erv;
        float e2 = el[n2 * H + h] + erv;
        float e3 = el[n3 * H + h] + erv;
        e0 = e0 > 0.f ? e0 : 0.2f * e0;
        e1 = e1 > 0.f ? e1 : 0.2f * e1;
        e2 = e2 > 0.f ? e2 : 0.2f * e2;
        e3 = e3 > 0.f ? e3 : 0.2f * e3;
        s0 += __expf(e0); s1 += __expf(e1); s2 += __expf(e2); s3 += __expf(e3);
    }
    for (; p < end; p++) {
        int n0 = csrc[p];
        float e0 = el[n0 * H + h] + erv;
        e0 = e0 > 0.f ? e0 : 0.2f * e0;
        s0 += __expf(e0);
    }
    float s = (s0 + s1) + (s2 + s3);
    float inv = 1.0f / s;

    float4 acc = make_float4(0.f, 0.f, 0.f, 0.f);
    const float4* ft4 = (const float4*)ft;
    p = beg;
    for (; p + 2 <= end; p += 2) {
        int n0 = csrc[p], n1 = csrc[p + 1];
        float e0 = el[n0 * H + h] + erv;
        float e1 = el[n1 * H + h] + erv;
        e0 = e0 > 0.f ? e0 : 0.2f * e0;
        e1 = e1 > 0.f ? e1 : 0.2f * e1;
        float a0 = __expf(e0) * inv;
        float a1 = __expf(e1) * inv;
        float4 f0 = ft4[n0 * 32 + lane];
        float4 f1 = ft4[n1 * 32 + lane];
        acc.x += f0.x * a0 + f1.x * a1;
        acc.y += f0.y * a0 + f1.y * a1;
        acc.z += f0.z * a0 + f1.z * a1;
        acc.w += f0.w * a0 + f1.w * a1;
    }
    for (; p < end; p++) {
        int n0 = csrc[p];
        float e0 = el[n0 * H + h] + erv;
        e0 = e0 > 0.f ? e0 : 0.2f * e0;
        float a0 = __expf(e0) * inv;
        float4 f0 = ft4[n0 * 32 + lane];
        acc.x += f0.x * a0;
        acc.y += f0.y * a0;
        acc.z += f0.z * a0;
        acc.w += f0.w * a0;
    }

    float4 xv = ((float4*)x)[node * 32 + lane];
    xv.x += acc.x > 0.f ? acc.x : expm1f(acc.x);
    xv.y += acc.y > 0.f ? acc.y : expm1f(acc.y);
    xv.z += acc.z > 0.f ? acc.z : expm1f(acc.z);
    xv.w += acc.w > 0.f ? acc.w : expm1f(acc.w);
    ((float4*)x)[node * 32 + lane] = xv;
}

// ---------------- fused edge MLP (tf32 tensor cores, fp16 p/q gather) ----------------
#define Y1_LD 132
__global__ void edge_mlp_tc(const int* __restrict__ src, const int* __restrict__ dst,
                            const uint2* __restrict__ p2, const uint2* __restrict__ q2,
                            const float* __restrict__ b1, const float* __restrict__ W2,
                            const float* __restrict__ b2, const float* __restrict__ W3,
                            const float* __restrict__ b3, float* __restrict__ out,
                            int E, int ntiles)
{
    extern __shared__ float dsm[];
    float*  y1s   = dsm;                         // 64*132 floats
    float2* Bfrag = (float2*)(dsm + 64 * Y1_LD); // [16 kt][8 nt][32 lane]

    __shared__ float outs[64][2][2];             // [edge][ch][nhalf]

    int t = threadIdx.x, lane = t & 31, warp = t >> 5;
    int tc = lane & 3, gr = lane >> 2;
    int mtile = warp & 3, nhalf = warp >> 2;

    for (int i = t; i < 16 * 8 * 32; i += 256) {
        int ln = i & 31, nt = (i >> 5) & 7, kt = i >> 8;
        int ltc = ln & 3, lgr = ln >> 2;
        float w0 = W2[(kt * 8 + ltc) * 64 + nt * 8 + lgr];
        float w1 = W2[(kt * 8 + ltc + 4) * 64 + nt * 8 + lgr];
        Bfrag[i] = make_float2(__uint_as_float(f2tf32(w0)), __uint_as_float(f2tf32(w1)));
    }

    float4 b1v = ((const float4*)b1)[lane];
    float bc0[4], bc1[4];
    float w3r[4][2][2];
#pragma unroll
    for (int nt = 0; nt < 4; nt++) {
        int col = nhalf * 32 + nt * 8 + tc * 2;
        bc0[nt] = b2[col];
        bc1[nt] = b2[col + 1];
        w3r[nt][0][0] = W3[col * 2];       w3r[nt][0][1] = W3[col * 2 + 1];
        w3r[nt][1][0] = W3[(col + 1) * 2]; w3r[nt][1][1] = W3[(col + 1) * 2 + 1];
    }
    float b30 = b3[0], b31 = b3[1];

    __syncthreads();

    for (int tile = blockIdx.x; tile < ntiles; tile += gridDim.x) {
        int ebase = tile * 64;

#pragma unroll
        for (int i = 0; i < 8; i++) {
            int row = warp * 8 + i;
            int eid = ebase + row;
            float4 y = make_float4(0.f, 0.f, 0.f, 0.f);
            if (eid < E) {
                int s = __ldg(&src[eid]), d = __ldg(&dst[eid]);
                uint2 pv = __ldg(&p2[s * 32 + lane]);
                uint2 qv = __ldg(&q2[d * 32 + lane]);
                float2 pa = __half22float2(*(__half2*)&pv.x);
                float2 pb = __half22float2(*(__half2*)&pv.y);
                float2 qa = __half22float2(*(__half2*)&qv.x);
                float2 qb = __half22float2(*(__half2*)&qv.y);
                y.x = fmaxf(pa.x + qa.x + b1v.x, 0.f);
                y.y = fmaxf(pa.y + qa.y + b1v.y, 0.f);
                y.z = fmaxf(pb.x + qb.x + b1v.z, 0.f);
                y.w = fmaxf(pb.y + qb.y + b1v.w, 0.f);
            }
            float4 yt;
            yt.x = __uint_as_float(f2tf32(y.x));
            yt.y = __uint_as_float(f2tf32(y.y));
            yt.z = __uint_as_float(f2tf32(y.z));
            yt.w = __uint_as_float(f2tf32(y.w));
            *(float4*)&y1s[row * Y1_LD + lane * 4] = yt;
        }
        __syncthreads();

        float c[4][4];
#pragma unroll
        for (int nt = 0; nt < 4; nt++) {
            c[nt][0] = bc0[nt]; c[nt][1] = bc1[nt];
            c[nt][2] = bc0[nt]; c[nt][3] = bc1[nt];
        }
        int m0 = mtile * 16;
        const float* Ar0 = y1s + (m0 + gr) * Y1_LD;
        const float* Ar1 = y1s + (m0 + gr + 8) * Y1_LD;
#pragma unroll
        for (int kt = 0; kt < 16; kt++) {
            int k0 = kt * 8;
            uint32_t a0 = __float_as_uint(Ar0[k0 + tc]);
            uint32_t a1 = __float_as_uint(Ar1[k0 + tc]);
            uint32_t a2 = __float_as_uint(Ar0[k0 + tc + 4]);
            uint32_t a3 = __float_as_uint(Ar1[k0 + tc + 4]);
            const float2* bk = Bfrag + (kt * 8 + nhalf * 4) * 32 + lane;
#pragma unroll
            for (int nt = 0; nt < 4; nt++) {
                float2 b = bk[nt * 32];
                mma_tf32(c[nt][0], c[nt][1], c[nt][2], c[nt][3],
                         a0, a1, a2, a3,
                         __float_as_uint(b.x), __float_as_uint(b.y));
            }
        }

        float pr00 = 0.f, pr01 = 0.f, pr10 = 0.f, pr11 = 0.f;
#pragma unroll
        for (int nt = 0; nt < 4; nt++) {
            float v0 = fmaxf(c[nt][0], 0.f);
            float v1 = fmaxf(c[nt][1], 0.f);
            float v2 = fmaxf(c[nt][2], 0.f);
            float v3 = fmaxf(c[nt][3], 0.f);
            pr00 += v0 * w3r[nt][0][0] + v1 * w3r[nt][1][0];
            pr01 += v0 * w3r[nt][0][1] + v1 * w3r[nt][1][1];
            pr10 += v2 * w3r[nt][0][0] + v3 * w3r[nt][1][0];
            pr11 += v2 * w3r[nt][0][1] + v3 * w3r[nt][1][1];
        }
#pragma unroll
        for (int off = 1; off <= 2; off <<= 1) {
            pr00 += __shfl_xor_sync(0xffffffffu, pr00, off);
            pr01 += __shfl_xor_sync(0xffffffffu, pr01, off);
            pr10 += __shfl_xor_sync(0xffffffffu, pr10, off);
            pr11 += __shfl_xor_sync(0xffffffffu, pr11, off);
        }
        if (tc == 0) {
            outs[m0 + gr][0][nhalf] = pr00;
            outs[m0 + gr][1][nhalf] = pr01;
            outs[m0 + gr + 8][0][nhalf] = pr10;
            outs[m0 + gr + 8][1][nhalf] = pr11;
        }
        __syncthreads();

        if (t < 128) {
            int e = t >> 1, ch = t & 1;
            int eid = ebase + e;
            if (eid < E)
                out[eid * 2 + ch] = outs[e][ch][0] + outs[e][ch][1] + (ch ? b31 : b30);
        }
        __syncthreads();
    }
}

// ---------------- host launcher ----------------
extern "C" void kernel_launch(void* const* d_in, const int* in_sizes, int n_in,
                              void* d_out, int out_size)
{
    const float* h     = (const float*)d_in[0];
    const int*   src   = (const int*)d_in[1];
    const int*   dst   = (const int*)d_in[2];
    const float* W_emb = (const float*)d_in[3];
    const float* b_emb = (const float*)d_in[4];
    const float* W_g   = (const float*)d_in[5];
    const float* al_g  = (const float*)d_in[6];
    const float* ar_g  = (const float*)d_in[7];
    const float* W_l   = (const float*)d_in[8];
    const float* al_l  = (const float*)d_in[9];
    const float* ar_l  = (const float*)d_in[10];
    const float* W1    = (const float*)d_in[11];
    const float* b1    = (const float*)d_in[12];
    const float* W2    = (const float*)d_in[13];
    const float* b2    = (const float*)d_in[14];
    const float* W3    = (const float*)d_in[15];
    const float* b3    = (const float*)d_in[16];
    float* out = (float*)d_out;

    int NN = in_sizes[0] / 128;
    int NE = in_sizes[1];

    float *x, *ft, *el, *er;
    __half *p, *q;
    int *deg, *cur, *rowstart, *csrc;
    float4* wpack;
    cudaGetSymbolAddress((void**)&x,   g_x);
    cudaGetSymbolAddress((void**)&ft,  g_ft);
    cudaGetSymbolAddress((void**)&el,  g_el);
    cudaGetSymbolAddress((void**)&er,  g_er);
    cudaGetSymbolAddress((void**)&p,   g_p);
    cudaGetSymbolAddress((void**)&q,   g_q);
    cudaGetSymbolAddress((void**)&deg, g_deg);
    cudaGetSymbolAddress((void**)&cur, g_cur);
    cudaGetSymbolAddress((void**)&rowstart, g_rowstart);
    cudaGetSymbolAddress((void**)&csrc, g_csrc);
    cudaGetSymbolAddress((void**)&wpack, g_wpack);

    const int FR = 16 * 16 * 32;   // float4 per packed matrix

    // ---- pack all 7 weight matrices ----
    pack_w<<<32, 256>>>(W_emb,              wpack + 0 * FR);
    pack_w<<<32, 256>>>(W_g,                wpack + 1 * FR);
    pack_w<<<32, 256>>>(W_g + 128 * 128,    wpack + 2 * FR);
    pack_w<<<32, 256>>>(W_g + 2 * 128 * 128, wpack + 3 * FR);
    pack_w<<<32, 256>>>(W_l,                wpack + 4 * FR);
    pack_w<<<32, 256>>>(W1,                 wpack + 5 * FR);
    pack_w<<<32, 256>>>(W1 + 128 * 128,     wpack + 6 * FR);

    // ---- CSR build (by dst) ----
    zero_int<<<(NN + 255) / 256, 256>>>(deg, NN);
    hist_dst<<<(NE + 255) / 256, 256>>>(dst, deg, NE);
    scan_deg<<<1, 1024>>>(deg, rowstart, cur, NN);
    scatter_csr<<<(NE + 255) / 256, 256>>>(src, dst, cur, csrc, NE);

    int gemm_blocks = (NN + 63) / 64;

    // ---- embedding ----
    gemm_tc<<<gemm_blocks, 128>>>(h, wpack + 0 * FR, b_emb, x, nullptr, NN, 0);

    // ---- 4 GAT layers ----
    for (int L = 0; L < 4; L++) {
        const float4* Wp = wpack + (size_t)(L + 1) * FR;
        const float* al = (L < 3) ? (al_g + (size_t)L * 128) : al_l;
        const float* ar = (L < 3) ? (ar_g + (size_t)L * 128) : ar_l;
        int H = (L < 3) ? 8 : 1;
        int logDh = (L < 3) ? 4 : 7;

        gemm_tc<<<gemm_blocks, 128>>>(x, Wp, nullptr, ft, nullptr, NN, 0);
        node_attn<<<(NN * 32 + 255) / 256, 256>>>(ft, al, ar, el, er, H, NN);
        gat_aggregate<<<(NN * 32 + 255) / 256, 256>>>(rowstart, csrc, ft, el, er, x,
                                                      H, logDh, NN);
    }

    // ---- node-side halves of he@W1 (fp16 outputs) ----
    gemm_tc<<<gemm_blocks, 128>>>(x, wpack + 5 * FR, nullptr, nullptr, p, NN, 1);
    gemm_tc<<<gemm_blocks, 128>>>(x, wpack + 6 * FR, nullptr, nullptr, q, NN, 1);

    // ---- fused edge MLP readout ----
    int ntiles = (NE + 63) / 64;
    size_t smem = 64 * Y1_LD * sizeof(float) + 16 * 8 * 32 * sizeof(float2);
    cudaFuncSetAttribute(edge_mlp_tc, cudaFuncAttributeMaxDynamicSharedMemorySize,
                         (int)smem);
    edge_mlp_tc<<<888, 256, smem>>>(src, dst, (const uint2*)p, (const uint2*)q,
                                    b1, W2, b2, W3, b3, out, NE, ntiles);
}

// round 5
// speedup vs baseline: 3.7698x; 1.2017x over previous
#include <cuda_runtime.h>
#include <cuda_bf16.h>
#include <cuda_fp16.h>
#include <math.h>
#include <stdint.h>

#define NMAX 50000
#define EMAX 1600000

// ---------------- scratch (static device globals; no allocation) ----------------
__device__ float  g_x[NMAX * 128];
__device__ __half g_ft[NMAX * 128];
__device__ float  g_el[NMAX * 8];
__device__ float  g_er[NMAX * 8];
__device__ __half g_p[NMAX * 128];
__device__ __half g_q[NMAX * 128];
__device__ int    g_deg[NMAX];
__device__ int    g_cur[NMAX];
__device__ int    g_rowstart[NMAX + 1];
__device__ int    g_csrc[EMAX];
__device__ uint2  g_wpack[7 * 8 * 16 * 32];   // 7 matrices, fp16 B-fragments

// ---------------- fp16 mma helper ----------------
__device__ __forceinline__ void mma_f16(float& c0, float& c1, float& c2, float& c3,
                                        uint32_t a0, uint32_t a1, uint32_t a2, uint32_t a3,
                                        uint32_t b0, uint32_t b1)
{
    asm volatile("mma.sync.aligned.m16n8k16.row.col.f32.f16.f16.f32 "
                 "{%0,%1,%2,%3}, {%4,%5,%6,%7}, {%8,%9}, {%0,%1,%2,%3};"
                 : "+f"(c0), "+f"(c1), "+f"(c2), "+f"(c3)
                 : "r"(a0), "r"(a1), "r"(a2), "r"(a3), "r"(b0), "r"(b1));
}

// ---------------- pack W[128,128] into fp16 B fragments ----------------
// out[(kt*16+nt)*32+lane] = {half2(W[k0+2tc][n], W[k0+2tc+1][n]),
//                            half2(W[k0+2tc+8][n], W[k0+2tc+9][n])}, n = nt*8+gr
__global__ void pack_w16(const float* __restrict__ W, uint2* __restrict__ out)
{
    int i = blockIdx.x * 256 + threadIdx.x;        // 4096 total
    int lane = i & 31, nt = (i >> 5) & 15, kt = i >> 9;
    int tc = lane & 3, gr = lane >> 2;
    int k0 = kt * 16, n = nt * 8 + gr;
    __half2 b0 = __floats2half2_rn(W[(k0 + 2 * tc) * 128 + n],
                                   W[(k0 + 2 * tc + 1) * 128 + n]);
    __half2 b1 = __floats2half2_rn(W[(k0 + 2 * tc + 8) * 128 + n],
                                   W[(k0 + 2 * tc + 9) * 128 + n]);
    uint2 u;
    u.x = *(uint32_t*)&b0;
    u.y = *(uint32_t*)&b1;
    out[i] = u;
}

// ---------------- fp16 GEMM: C[M,128] = A[M,128] @ W (packed) (+bias) ----------------
// 128 threads / 4 warps, 64 rows per block. mode 0: fp32 out; mode 1: fp16 out.
__global__ __launch_bounds__(128)
void gemm_f16(const float* __restrict__ A, const uint2* __restrict__ Bp,
              const float* __restrict__ bias, float* __restrict__ Cf,
              __half2* __restrict__ Ch, int M, int mode)
{
    __shared__ __half As[64 * 136];   // 17.4KB, padded
    __shared__ uint2  Bs[4096];       // 32KB fragment-ordered W
    int t = threadIdx.x, lane = t & 31, warp = t >> 5;
    int tc = lane & 3, gr = lane >> 2;
    int row0 = blockIdx.x * 64;

#pragma unroll
    for (int i = 0; i < 32; i++) Bs[t + i * 128] = __ldg(&Bp[t + i * 128]);

    const float4* A4 = (const float4*)A;
#pragma unroll
    for (int i = 0; i < 16; i++) {
        int f = t + i * 128;
        int r = f >> 5, c4 = f & 31;
        int grow = row0 + r;
        float4 v = (grow < M) ? A4[grow * 32 + c4] : make_float4(0.f, 0.f, 0.f, 0.f);
        __half2 h0 = __floats2half2_rn(v.x, v.y);
        __half2 h1 = __floats2half2_rn(v.z, v.w);
        uint2 u;
        u.x = *(uint32_t*)&h0;
        u.y = *(uint32_t*)&h1;
        *(uint2*)&As[r * 136 + c4 * 4] = u;
    }
    __syncthreads();

    float c[16][4];
#pragma unroll
    for (int nt = 0; nt < 16; nt++)
#pragma unroll
        for (int j = 0; j < 4; j++) c[nt][j] = 0.f;

    int m0 = warp * 16;
    const __half* Ar0 = As + (m0 + gr) * 136;
    const __half* Ar1 = Ar0 + 8 * 136;

#pragma unroll
    for (int kt = 0; kt < 8; kt++) {
        int k0 = kt * 16;
        uint32_t a0 = *(const uint32_t*)&Ar0[k0 + 2 * tc];
        uint32_t a1 = *(const uint32_t*)&Ar1[k0 + 2 * tc];
        uint32_t a2 = *(const uint32_t*)&Ar0[k0 + 2 * tc + 8];
        uint32_t a3 = *(const uint32_t*)&Ar1[k0 + 2 * tc + 8];
        const uint2* bk = Bs + kt * 16 * 32 + lane;
#pragma unroll
        for (int nt = 0; nt < 16; nt++) {
            uint2 b = bk[nt * 32];
            mma_f16(c[nt][0], c[nt][1], c[nt][2], c[nt][3],
                    a0, a1, a2, a3, b.x, b.y);
        }
    }

    int r0 = row0 + m0 + gr;
    int r1 = r0 + 8;
#pragma unroll
    for (int nt = 0; nt < 16; nt++) {
        int col = nt * 8 + tc * 2;
        float b0 = 0.f, b1 = 0.f;
        if (bias) { b0 = __ldg(&bias[col]); b1 = __ldg(&bias[col + 1]); }
        float v00 = c[nt][0] + b0, v01 = c[nt][1] + b1;
        float v10 = c[nt][2] + b0, v11 = c[nt][3] + b1;
        if (mode == 0) {
            if (r0 < M) *(float2*)&Cf[r0 * 128 + col] = make_float2(v00, v01);
            if (r1 < M) *(float2*)&Cf[r1 * 128 + col] = make_float2(v10, v11);
        } else {
            if (r0 < M) Ch[r0 * 64 + nt * 4 + tc] = __floats2half2_rn(v00, v01);
            if (r1 < M) Ch[r1 * 64 + nt * 4 + tc] = __floats2half2_rn(v10, v11);
        }
    }
}

// ---------------- CSR build ----------------
__global__ void zero_int(int* __restrict__ a, int n)
{
    int i = blockIdx.x * blockDim.x + threadIdx.x;
    if (i < n) a[i] = 0;
}

__global__ void hist_dst(const int* __restrict__ dst, int* __restrict__ deg, int E)
{
    int e = blockIdx.x * blockDim.x + threadIdx.x;
    if (e < E) atomicAdd(&deg[dst[e]], 1);
}

__global__ void scan_deg(const int* __restrict__ deg, int* __restrict__ rowstart,
                         int* __restrict__ cursor, int n)
{
    __shared__ int sums[1024];
    int t = threadIdx.x;
    int chunk = (n + 1023) / 1024;
    int beg = t * chunk;
    int end = beg + chunk < n ? beg + chunk : n;
    int s = 0;
    for (int i = beg; i < end; i++) s += deg[i];
    sums[t] = s;
    __syncthreads();
    for (int off = 1; off < 1024; off <<= 1) {
        int v = (t >= off) ? sums[t - off] : 0;
        __syncthreads();
        sums[t] += v;
        __syncthreads();
    }
    int excl = (t == 0) ? 0 : sums[t - 1];
    for (int i = beg; i < end; i++) {
        int d = deg[i];
        rowstart[i] = excl;
        cursor[i] = excl;
        excl += d;
    }
    if (t == 1023) rowstart[n] = sums[1023];
}

__global__ void scatter_csr(const int* __restrict__ src, const int* __restrict__ dst,
                            int* __restrict__ cur, int* __restrict__ csrc, int E)
{
    int e = blockIdx.x * blockDim.x + threadIdx.x;
    if (e >= E) return;
    int p = atomicAdd(&cur[dst[e]], 1);
    csrc[p] = src[e];
}

// ---------------- per-node attention logits: warp per node (ft fp16) ----------------
__global__ void node_attn(const __half* __restrict__ ft, const float* __restrict__ al,
                          const float* __restrict__ ar, float* __restrict__ el,
                          float* __restrict__ er, int H, int M)
{
    int node = (blockIdx.x * blockDim.x + threadIdx.x) >> 5;
    int lane = threadIdx.x & 31;
    if (node >= M) return;
    uint2 fv = ((const uint2*)ft)[node * 32 + lane];
    float2 f0 = __half22float2(*(__half2*)&fv.x);
    float2 f1 = __half22float2(*(__half2*)&fv.y);
    float4 a = ((const float4*)al)[lane];
    float4 b = ((const float4*)ar)[lane];
    float pe = f0.x * a.x + f0.y * a.y + f1.x * a.z + f1.y * a.w;
    float pr = f0.x * b.x + f0.y * b.y + f1.x * b.z + f1.y * b.w;
    int glanes = 32 / H;
#pragma unroll
    for (int off = 1; off < 32; off <<= 1) {
        if (off < glanes) {
            pe += __shfl_xor_sync(0xffffffffu, pe, off);
            pr += __shfl_xor_sync(0xffffffffu, pr, off);
        }
    }
    if ((lane & (glanes - 1)) == 0) {
        int h = lane / glanes;
        el[node * H + h] = pe;
        er[node * H + h] = pr;
    }
}

// ---------------- GAT aggregation: warp per node, no atomics (ft fp16) ----------------
__global__ void gat_aggregate(const int* __restrict__ rowstart, const int* __restrict__ csrc,
                              const __half* __restrict__ ft, const float* __restrict__ el,
                              const float* __restrict__ er, float* __restrict__ x,
                              int H, int logDh, int NN)
{
    int node = (blockIdx.x * blockDim.x + threadIdx.x) >> 5;
    int lane = threadIdx.x & 31;
    if (node >= NN) return;
    int h = (lane * 4) >> logDh;
    float erv = er[node * H + h];
    int beg = rowstart[node], end = rowstart[node + 1];

    float s0 = 0.f, s1 = 0.f, s2 = 0.f, s3 = 0.f;
    int p = beg;
    for (; p + 4 <= end; p += 4) {
        int n0 = csrc[p], n1 = csrc[p + 1], n2 = csrc[p + 2], n3 = csrc[p + 3];
        float e0 = el[n0 * H + h] + erv;
        float e1 = el[n1 * H + h] + erv;
        float e2 = el[n2 * H + h] + erv;
        float e3 = el[n3 * H + h] + erv;
        e0 = e0 > 0.f ? e0 : 0.2f * e0;
        e1 = e1 > 0.f ? e1 : 0.2f * e1;
        e2 = e2 > 0.f ? e2 : 0.2f * e2;
        e3 = e3 > 0.f ? e3 : 0.2f * e3;
        s0 += __expf(e0); s1 += __expf(e1); s2 += __expf(e2); s3 += __expf(e3);
    }
    for (; p < end; p++) {
        int n0 = csrc[p];
        float e0 = el[n0 * H + h] + erv;
        e0 = e0 > 0.f ? e0 : 0.2f * e0;
        s0 += __expf(e0);
    }
    float s = (s0 + s1) + (s2 + s3);
    float inv = 1.0f / s;

    float4 acc = make_float4(0.f, 0.f, 0.f, 0.f);
    const uint2* ftu = (const uint2*)ft;
    p = beg;
    for (; p + 2 <= end; p += 2) {
        int n0 = csrc[p], n1 = csrc[p + 1];
        float e0 = el[n0 * H + h] + erv;
        float e1 = el[n1 * H + h] + erv;
        e0 = e0 > 0.f ? e0 : 0.2f * e0;
        e1 = e1 > 0.f ? e1 : 0.2f * e1;
        float a0 = __expf(e0) * inv;
        float a1 = __expf(e1) * inv;
        uint2 u0 = __ldg(&ftu[n0 * 32 + lane]);
        uint2 u1 = __ldg(&ftu[n1 * 32 + lane]);
        float2 f0a = __half22float2(*(__half2*)&u0.x);
        float2 f0b = __half22float2(*(__half2*)&u0.y);
        float2 f1a = __half22float2(*(__half2*)&u1.x);
        float2 f1b = __half22float2(*(__half2*)&u1.y);
        acc.x += f0a.x * a0 + f1a.x * a1;
        acc.y += f0a.y * a0 + f1a.y * a1;
        acc.z += f0b.x * a0 + f1b.x * a1;
        acc.w += f0b.y * a0 + f1b.y * a1;
    }
    for (; p < end; p++) {
        int n0 = csrc[p];
        float e0 = el[n0 * H + h] + erv;
        e0 = e0 > 0.f ? e0 : 0.2f * e0;
        float a0 = __expf(e0) * inv;
        uint2 u0 = __ldg(&ftu[n0 * 32 + lane]);
        float2 f0a = __half22float2(*(__half2*)&u0.x);
        float2 f0b = __half22float2(*(__half2*)&u0.y);
        acc.x += f0a.x * a0;
        acc.y += f0a.y * a0;
        acc.z += f0b.x * a0;
        acc.w += f0b.y * a0;
    }

    float4 xv = ((float4*)x)[node * 32 + lane];
    xv.x += acc.x > 0.f ? acc.x : expm1f(acc.x);
    xv.y += acc.y > 0.f ? acc.y : expm1f(acc.y);
    xv.z += acc.z > 0.f ? acc.z : expm1f(acc.z);
    xv.w += acc.w > 0.f ? acc.w : expm1f(acc.w);
    ((float4*)x)[node * 32 + lane] = xv;
}

// ---------------- fused edge MLP (fp16 tensor cores) ----------------
// 256 threads / 8 warps, 64 edges per tile. y1 half [64][136]; W2 half fragments.
__global__ void edge_mlp_tc(const int* __restrict__ src, const int* __restrict__ dst,
                            const uint2* __restrict__ p2, const uint2* __restrict__ q2,
                            const float* __restrict__ b1, const float* __restrict__ W2,
                            const float* __restrict__ b2, const float* __restrict__ W3,
                            const float* __restrict__ b3, float* __restrict__ out,
                            int E, int ntiles)
{
    extern __shared__ __half dsm[];
    __half* y1s   = dsm;                           // 64*136 halves (17408B)
    uint2*  Bfrag = (uint2*)(dsm + 64 * 136);      // [8 kt][8 nt][32 lane] (16KB)

    __shared__ float outs[64][2][2];               // [edge][ch][nhalf]

    int t = threadIdx.x, lane = t & 31, warp = t >> 5;
    int tc = lane & 3, gr = lane >> 2;
    int mtile = warp & 3, nhalf = warp >> 2;

    // pack W2[128,64] into fp16 fragments (once per block)
    for (int i = t; i < 8 * 8 * 32; i += 256) {
        int ln = i & 31, nt = (i >> 5) & 7, kt = i >> 8;
        int ltc = ln & 3, lgr = ln >> 2;
        int k0 = kt * 16, n = nt * 8 + lgr;
        __half2 h0 = __floats2half2_rn(W2[(k0 + 2 * ltc) * 64 + n],
                                       W2[(k0 + 2 * ltc + 1) * 64 + n]);
        __half2 h1 = __floats2half2_rn(W2[(k0 + 2 * ltc + 8) * 64 + n],
                                       W2[(k0 + 2 * ltc + 9) * 64 + n]);
        uint2 u;
        u.x = *(uint32_t*)&h0;
        u.y = *(uint32_t*)&h1;
        Bfrag[i] = u;
    }

    float4 b1v = ((const float4*)b1)[lane];
    float bc0[4], bc1[4];
    float w3r[4][2][2];
#pragma unroll
    for (int nt = 0; nt < 4; nt++) {
        int col = nhalf * 32 + nt * 8 + tc * 2;
        bc0[nt] = b2[col];
        bc1[nt] = b2[col + 1];
        w3r[nt][0][0] = W3[col * 2];       w3r[nt][0][1] = W3[col * 2 + 1];
        w3r[nt][1][0] = W3[(col + 1) * 2]; w3r[nt][1][1] = W3[(col + 1) * 2 + 1];
    }
    float b30 = b3[0], b31 = b3[1];

    __syncthreads();

    for (int tile = blockIdx.x; tile < ntiles; tile += gridDim.x) {
        int ebase = tile * 64;

#pragma unroll
        for (int i = 0; i < 8; i++) {
            int row = warp * 8 + i;
            int eid = ebase + row;
            float4 y = make_float4(0.f, 0.f, 0.f, 0.f);
            if (eid < E) {
                int s = __ldg(&src[eid]), d = __ldg(&dst[eid]);
                uint2 pv = __ldg(&p2[s * 32 + lane]);
                uint2 qv = __ldg(&q2[d * 32 + lane]);
                float2 pa = __half22float2(*(__half2*)&pv.x);
                float2 pb = __half22float2(*(__half2*)&pv.y);
                float2 qa = __half22float2(*(__half2*)&qv.x);
                float2 qb = __half22float2(*(__half2*)&qv.y);
                y.x = fmaxf(pa.x + qa.x + b1v.x, 0.f);
                y.y = fmaxf(pa.y + qa.y + b1v.y, 0.f);
                y.z = fmaxf(pb.x + qb.x + b1v.z, 0.f);
                y.w = fmaxf(pb.y + qb.y + b1v.w, 0.f);
            }
            __half2 h0 = __floats2half2_rn(y.x, y.y);
            __half2 h1 = __floats2half2_rn(y.z, y.w);
            uint2 u;
            u.x = *(uint32_t*)&h0;
            u.y = *(uint32_t*)&h1;
            *(uint2*)&y1s[row * 136 + lane * 4] = u;
        }
        __syncthreads();

        float c[4][4];
#pragma unroll
        for (int nt = 0; nt < 4; nt++) {
            c[nt][0] = bc0[nt]; c[nt][1] = bc1[nt];
            c[nt][2] = bc0[nt]; c[nt][3] = bc1[nt];
        }
        int m0 = mtile * 16;
        const __half* Ar0 = y1s + (m0 + gr) * 136;
        const __half* Ar1 = Ar0 + 8 * 136;
#pragma unroll
        for (int kt = 0; kt < 8; kt++) {
            int k0 = kt * 16;
            uint32_t a0 = *(const uint32_t*)&Ar0[k0 + 2 * tc];
            uint32_t a1 = *(const uint32_t*)&Ar1[k0 + 2 * tc];
            uint32_t a2 = *(const uint32_t*)&Ar0[k0 + 2 * tc + 8];
            uint32_t a3 = *(const uint32_t*)&Ar1[k0 + 2 * tc + 8];
            const uint2* bk = Bfrag + (kt * 8 + nhalf * 4) * 32 + lane;
#pragma unroll
            for (int nt = 0; nt < 4; nt++) {
                uint2 b = bk[nt * 32];
                mma_f16(c[nt][0], c[nt][1], c[nt][2], c[nt][3],
                        a0, a1, a2, a3, b.x, b.y);
            }
        }

        float pr00 = 0.f, pr01 = 0.f, pr10 = 0.f, pr11 = 0.f;
#pragma unroll
        for (int nt = 0; nt < 4; nt++) {
            float v0 = fmaxf(c[nt][0], 0.f);
            float v1 = fmaxf(c[nt][1], 0.f);
            float v2 = fmaxf(c[nt][2], 0.f);
            float v3 = fmaxf(c[nt][3], 0.f);
            pr00 += v0 * w3r[nt][0][0] + v1 * w3r[nt][1][0];
            pr01 += v0 * w3r[nt][0][1] + v1 * w3r[nt][1][1];
            pr10 += v2 * w3r[nt][0][0] + v3 * w3r[nt][1][0];
            pr11 += v2 * w3r[nt][0][1] + v3 * w3r[nt][1][1];
        }
#pragma unroll
        for (int off = 1; off <= 2; off <<= 1) {
            pr00 += __shfl_xor_sync(0xffffffffu, pr00, off);
            pr01 += __shfl_xor_sync(0xffffffffu, pr01, off);
            pr10 += __shfl_xor_sync(0xffffffffu, pr10, off);
            pr11 += __shfl_xor_sync(0xffffffffu, pr11, off);
        }
        if (tc == 0) {
            outs[m0 + gr][0][nhalf] = pr00;
            outs[m0 + gr][1][nhalf] = pr01;
            outs[m0 + gr + 8][0][nhalf] = pr10;
            outs[m0 + gr + 8][1][nhalf] = pr11;
        }
        __syncthreads();

        if (t < 128) {
            int e = t >> 1, ch = t & 1;
            int eid = ebase + e;
            if (eid < E)
                out[eid * 2 + ch] = outs[e][ch][0] + outs[e][ch][1] + (ch ? b31 : b30);
        }
        __syncthreads();
    }
}

// ---------------- host launcher ----------------
extern "C" void kernel_launch(void* const* d_in, const int* in_sizes, int n_in,
                              void* d_out, int out_size)
{
    const float* h     = (const float*)d_in[0];
    const int*   src   = (const int*)d_in[1];
    const int*   dst   = (const int*)d_in[2];
    const float* W_emb = (const float*)d_in[3];
    const float* b_emb = (const float*)d_in[4];
    const float* W_g   = (const float*)d_in[5];
    const float* al_g  = (const float*)d_in[6];
    const float* ar_g  = (const float*)d_in[7];
    const float* W_l   = (const float*)d_in[8];
    const float* al_l  = (const float*)d_in[9];
    const float* ar_l  = (const float*)d_in[10];
    const float* W1    = (const float*)d_in[11];
    const float* b1    = (const float*)d_in[12];
    const float* W2    = (const float*)d_in[13];
    const float* b2    = (const float*)d_in[14];
    const float* W3    = (const float*)d_in[15];
    const float* b3    = (const float*)d_in[16];
    float* out = (float*)d_out;

    int NN = in_sizes[0] / 128;
    int NE = in_sizes[1];

    float *x, *el, *er;
    __half *ft, *p, *q;
    int *deg, *cur, *rowstart, *csrc;
    uint2* wpack;
    cudaGetSymbolAddress((void**)&x,   g_x);
    cudaGetSymbolAddress((void**)&ft,  g_ft);
    cudaGetSymbolAddress((void**)&el,  g_el);
    cudaGetSymbolAddress((void**)&er,  g_er);
    cudaGetSymbolAddress((void**)&p,   g_p);
    cudaGetSymbolAddress((void**)&q,   g_q);
    cudaGetSymbolAddress((void**)&deg, g_deg);
    cudaGetSymbolAddress((void**)&cur, g_cur);
    cudaGetSymbolAddress((void**)&rowstart, g_rowstart);
    cudaGetSymbolAddress((void**)&csrc, g_csrc);
    cudaGetSymbolAddress((void**)&wpack, g_wpack);

    const int FR = 8 * 16 * 32;   // uint2 per packed matrix

    // ---- pack all 7 weight matrices into fp16 fragments ----
    pack_w16<<<16, 256>>>(W_emb,               wpack + 0 * FR);
    pack_w16<<<16, 256>>>(W_g,                 wpack + 1 * FR);
    pack_w16<<<16, 256>>>(W_g + 128 * 128,     wpack + 2 * FR);
    pack_w16<<<16, 256>>>(W_g + 2 * 128 * 128, wpack + 3 * FR);
    pack_w16<<<16, 256>>>(W_l,                 wpack + 4 * FR);
    pack_w16<<<16, 256>>>(W1,                  wpack + 5 * FR);
    pack_w16<<<16, 256>>>(W1 + 128 * 128,      wpack + 6 * FR);

    // ---- CSR build (by dst) ----
    zero_int<<<(NN + 255) / 256, 256>>>(deg, NN);
    hist_dst<<<(NE + 255) / 256, 256>>>(dst, deg, NE);
    scan_deg<<<1, 1024>>>(deg, rowstart, cur, NN);
    scatter_csr<<<(NE + 255) / 256, 256>>>(src, dst, cur, csrc, NE);

    int gemm_blocks = (NN + 63) / 64;

    // ---- embedding (fp32 out) ----
    gemm_f16<<<gemm_blocks, 128>>>(h, wpack + 0 * FR, b_emb, x, nullptr, NN, 0);

    // ---- 4 GAT layers ----
    for (int L = 0; L < 4; L++) {
        const uint2* Wp = wpack + (size_t)(L + 1) * FR;
        const float* al = (L < 3) ? (al_g + (size_t)L * 128) : al_l;
        const float* ar = (L < 3) ? (ar_g + (size_t)L * 128) : ar_l;
        int H = (L < 3) ? 8 : 1;
        int logDh = (L < 3) ? 4 : 7;

        gemm_f16<<<gemm_blocks, 128>>>(x, Wp, nullptr, nullptr, (__half2*)ft, NN, 1);
        node_attn<<<(NN * 32 + 255) / 256, 256>>>(ft, al, ar, el, er, H, NN);
        gat_aggregate<<<(NN * 32 + 255) / 256, 256>>>(rowstart, csrc, ft, el, er, x,
                                                      H, logDh, NN);
    }

    // ---- node-side halves of he@W1 (fp16 outputs) ----
    gemm_f16<<<gemm_blocks, 128>>>(x, wpack + 5 * FR, nullptr, nullptr, (__half2*)p, NN, 1);
    gemm_f16<<<gemm_blocks, 128>>>(x, wpack + 6 * FR, nullptr, nullptr, (__half2*)q, NN, 1);

    // ---- fused edge MLP readout ----
    int ntiles = (NE + 63) / 64;
    size_t smem = 64 * 136 * sizeof(__half) + 8 * 8 * 32 * sizeof(uint2);
    edge_mlp_tc<<<1184, 256, smem>>>(src, dst, (const uint2*)p, (const uint2*)q,
                                     b1, W2, b2, W3, b3, out, NE, ntiles);
}

// round 6
// speedup vs baseline: 4.4525x; 1.1811x over previous
#include <cuda_runtime.h>
#include <cuda_bf16.h>
#include <cuda_fp16.h>
#include <math.h>
#include <stdint.h>

#define NMAX 50000
#define EMAX 1600000

// ---------------- scratch (static device globals; no allocation) ----------------
__device__ float  g_x[NMAX * 128];
__device__ __half g_ft[NMAX * 128];
__device__ float  g_el[NMAX * 8];
__device__ float  g_er[NMAX * 8];
__device__ __half g_p[NMAX * 128];
__device__ __half g_q[NMAX * 128];
__device__ int    g_deg[NMAX];
__device__ int    g_cur[NMAX];
__device__ int    g_rowstart[NMAX + 1];
__device__ int    g_csrc[EMAX];
__device__ uint2  g_wpack[7 * 8 * 16 * 32];   // 7 matrices, fp16 B-fragments

// ---------------- fp16 mma helper ----------------
__device__ __forceinline__ void mma_f16(float& c0, float& c1, float& c2, float& c3,
                                        uint32_t a0, uint32_t a1, uint32_t a2, uint32_t a3,
                                        uint32_t b0, uint32_t b1)
{
    asm volatile("mma.sync.aligned.m16n8k16.row.col.f32.f16.f16.f32 "
                 "{%0,%1,%2,%3}, {%4,%5,%6,%7}, {%8,%9}, {%0,%1,%2,%3};"
                 : "+f"(c0), "+f"(c1), "+f"(c2), "+f"(c3)
                 : "r"(a0), "r"(a1), "r"(a2), "r"(a3), "r"(b0), "r"(b1));
}

// ---------------- pack W[128,128] into fp16 B fragments ----------------
__global__ void pack_w16(const float* __restrict__ W, uint2* __restrict__ out)
{
    int i = blockIdx.x * 256 + threadIdx.x;        // 4096 total
    int lane = i & 31, nt = (i >> 5) & 15, kt = i >> 9;
    int tc = lane & 3, gr = lane >> 2;
    int k0 = kt * 16, n = nt * 8 + gr;
    __half2 b0 = __floats2half2_rn(W[(k0 + 2 * tc) * 128 + n],
                                   W[(k0 + 2 * tc + 1) * 128 + n]);
    __half2 b1 = __floats2half2_rn(W[(k0 + 2 * tc + 8) * 128 + n],
                                   W[(k0 + 2 * tc + 9) * 128 + n]);
    uint2 u;
    u.x = *(uint32_t*)&b0;
    u.y = *(uint32_t*)&b1;
    out[i] = u;
}

// ---------------- fp16 GEMM + optional fused attention logits ----------------
// H=0: no attn. OUT=0: fp32 C; OUT=1: fp16 C.
template<int H, int OUT>
__global__ __launch_bounds__(128)
void gemm_f16(const float* __restrict__ A, const uint2* __restrict__ Bp,
              const float* __restrict__ bias, float* __restrict__ Cf,
              __half2* __restrict__ Ch,
              const float* __restrict__ alp, const float* __restrict__ arp,
              float* __restrict__ el, float* __restrict__ er, int M)
{
    __shared__ __half As[64 * 136];
    __shared__ uint2  Bs[4096];
    int t = threadIdx.x, lane = t & 31, warp = t >> 5;
    int tc = lane & 3, gr = lane >> 2;
    int row0 = blockIdx.x * 64;

#pragma unroll
    for (int i = 0; i < 32; i++) Bs[t + i * 128] = __ldg(&Bp[t + i * 128]);

    const float4* A4 = (const float4*)A;
#pragma unroll
    for (int i = 0; i < 16; i++) {
        int f = t + i * 128;
        int r = f >> 5, c4 = f & 31;
        int grow = row0 + r;
        float4 v = (grow < M) ? A4[grow * 32 + c4] : make_float4(0.f, 0.f, 0.f, 0.f);
        __half2 h0 = __floats2half2_rn(v.x, v.y);
        __half2 h1 = __floats2half2_rn(v.z, v.w);
        uint2 u;
        u.x = *(uint32_t*)&h0;
        u.y = *(uint32_t*)&h1;
        *(uint2*)&As[r * 136 + c4 * 4] = u;
    }
    __syncthreads();

    float c[16][4];
#pragma unroll
    for (int nt = 0; nt < 16; nt++)
#pragma unroll
        for (int j = 0; j < 4; j++) c[nt][j] = 0.f;

    int m0 = warp * 16;
    const __half* Ar0 = As + (m0 + gr) * 136;
    const __half* Ar1 = Ar0 + 8 * 136;

#pragma unroll
    for (int kt = 0; kt < 8; kt++) {
        int k0 = kt * 16;
        uint32_t a0 = *(const uint32_t*)&Ar0[k0 + 2 * tc];
        uint32_t a1 = *(const uint32_t*)&Ar1[k0 + 2 * tc];
        uint32_t a2 = *(const uint32_t*)&Ar0[k0 + 2 * tc + 8];
        uint32_t a3 = *(const uint32_t*)&Ar1[k0 + 2 * tc + 8];
        const uint2* bk = Bs + kt * 16 * 32 + lane;
#pragma unroll
        for (int nt = 0; nt < 16; nt++) {
            uint2 b = bk[nt * 32];
            mma_f16(c[nt][0], c[nt][1], c[nt][2], c[nt][3],
                    a0, a1, a2, a3, b.x, b.y);
        }
    }

    int r0 = row0 + m0 + gr;
    int r1 = r0 + 8;

    // ---- fused attention logits ----
    if (H > 0) {
        constexpr int HH = (H > 0) ? H : 1;
        float el0[HH], er0[HH], el1[HH], er1[HH];
#pragma unroll
        for (int hh = 0; hh < HH; hh++) { el0[hh] = er0[hh] = el1[hh] = er1[hh] = 0.f; }
#pragma unroll
        for (int nt = 0; nt < 16; nt++) {
            int col = nt * 8 + tc * 2;
            constexpr int dummy = 0; (void)dummy;
            int hh = (nt * H) >> 4;      // compile-time per unrolled nt
            float a0 = __ldg(&alp[col]), a1 = __ldg(&alp[col + 1]);
            float g0 = __ldg(&arp[col]), g1 = __ldg(&arp[col + 1]);
            el0[hh] += c[nt][0] * a0 + c[nt][1] * a1;
            er0[hh] += c[nt][0] * g0 + c[nt][1] * g1;
            el1[hh] += c[nt][2] * a0 + c[nt][3] * a1;
            er1[hh] += c[nt][2] * g0 + c[nt][3] * g1;
        }
#pragma unroll
        for (int hh = 0; hh < HH; hh++) {
            el0[hh] += __shfl_xor_sync(0xffffffffu, el0[hh], 1);
            el0[hh] += __shfl_xor_sync(0xffffffffu, el0[hh], 2);
            er0[hh] += __shfl_xor_sync(0xffffffffu, er0[hh], 1);
            er0[hh] += __shfl_xor_sync(0xffffffffu, er0[hh], 2);
            el1[hh] += __shfl_xor_sync(0xffffffffu, el1[hh], 1);
            el1[hh] += __shfl_xor_sync(0xffffffffu, el1[hh], 2);
            er1[hh] += __shfl_xor_sync(0xffffffffu, er1[hh], 1);
            er1[hh] += __shfl_xor_sync(0xffffffffu, er1[hh], 2);
        }
        if (tc == 0) {
#pragma unroll
            for (int hh = 0; hh < HH; hh++) {
                if (r0 < M) { el[r0 * HH + hh] = el0[hh]; er[r0 * HH + hh] = er0[hh]; }
                if (r1 < M) { el[r1 * HH + hh] = el1[hh]; er[r1 * HH + hh] = er1[hh]; }
            }
        }
    }

#pragma unroll
    for (int nt = 0; nt < 16; nt++) {
        int col = nt * 8 + tc * 2;
        float b0 = 0.f, b1 = 0.f;
        if (bias) { b0 = __ldg(&bias[col]); b1 = __ldg(&bias[col + 1]); }
        float v00 = c[nt][0] + b0, v01 = c[nt][1] + b1;
        float v10 = c[nt][2] + b0, v11 = c[nt][3] + b1;
        if (OUT == 0) {
            if (r0 < M) *(float2*)&Cf[r0 * 128 + col] = make_float2(v00, v01);
            if (r1 < M) *(float2*)&Cf[r1 * 128 + col] = make_float2(v10, v11);
        } else {
            if (r0 < M) Ch[r0 * 64 + nt * 4 + tc] = __floats2half2_rn(v00, v01);
            if (r1 < M) Ch[r1 * 64 + nt * 4 + tc] = __floats2half2_rn(v10, v11);
        }
    }
}

// ---------------- CSR build ----------------
__global__ void zero_int(int* __restrict__ a, int n)
{
    int i = blockIdx.x * blockDim.x + threadIdx.x;
    if (i < n) a[i] = 0;
}

__global__ void hist_dst(const int* __restrict__ dst, int* __restrict__ deg, int E)
{
    int e = blockIdx.x * blockDim.x + threadIdx.x;
    if (e < E) atomicAdd(&deg[dst[e]], 1);
}

__global__ void scan_deg(const int* __restrict__ deg, int* __restrict__ rowstart,
                         int* __restrict__ cursor, int n)
{
    __shared__ int sums[1024];
    int t = threadIdx.x;
    int chunk = (n + 1023) / 1024;
    int beg = t * chunk;
    int end = beg + chunk < n ? beg + chunk : n;
    int s = 0;
    for (int i = beg; i < end; i++) s += deg[i];
    sums[t] = s;
    __syncthreads();
    for (int off = 1; off < 1024; off <<= 1) {
        int v = (t >= off) ? sums[t - off] : 0;
        __syncthreads();
        sums[t] += v;
        __syncthreads();
    }
    int excl = (t == 0) ? 0 : sums[t - 1];
    for (int i = beg; i < end; i++) {
        int d = deg[i];
        rowstart[i] = excl;
        cursor[i] = excl;
        excl += d;
    }
    if (t == 1023) rowstart[n] = sums[1023];
}

__global__ void scatter_csr(const int* __restrict__ src, const int* __restrict__ dst,
                            int* __restrict__ cur, int* __restrict__ csrc, int E)
{
    int e = blockIdx.x * blockDim.x + threadIdx.x;
    if (e >= E) return;
    int p = atomicAdd(&cur[dst[e]], 1);
    csrc[p] = src[e];
}

// ---------------- GAT aggregation: single-pass, warp per node ----------------
// out = (sum_j w_j ft_j) / (sum_j w_j) ; softmax max-shift removed (logits O(1)).
__global__ void gat_aggregate(const int* __restrict__ rowstart, const int* __restrict__ csrc,
                              const __half* __restrict__ ft, const float* __restrict__ el,
                              const float* __restrict__ er, float* __restrict__ x,
                              int H, int logDh, int NN)
{
    int node = (blockIdx.x * blockDim.x + threadIdx.x) >> 5;
    int lane = threadIdx.x & 31;
    if (node >= NN) return;
    int h = (lane * 4) >> logDh;
    float erv = er[node * H + h];
    int beg = rowstart[node], end = rowstart[node + 1];

    float s = 0.f;
    float4 acc = make_float4(0.f, 0.f, 0.f, 0.f);
    const uint2* ftu = (const uint2*)ft;
    int p = beg;
    for (; p + 2 <= end; p += 2) {
        int n0 = csrc[p], n1 = csrc[p + 1];
        float e0 = el[n0 * H + h] + erv;
        float e1 = el[n1 * H + h] + erv;
        e0 = e0 > 0.f ? e0 : 0.2f * e0;
        e1 = e1 > 0.f ? e1 : 0.2f * e1;
        float w0 = __expf(e0);
        float w1 = __expf(e1);
        uint2 u0 = __ldg(&ftu[n0 * 32 + lane]);
        uint2 u1 = __ldg(&ftu[n1 * 32 + lane]);
        s += w0 + w1;
        float2 f0a = __half22float2(*(__half2*)&u0.x);
        float2 f0b = __half22float2(*(__half2*)&u0.y);
        float2 f1a = __half22float2(*(__half2*)&u1.x);
        float2 f1b = __half22float2(*(__half2*)&u1.y);
        acc.x += f0a.x * w0 + f1a.x * w1;
        acc.y += f0a.y * w0 + f1a.y * w1;
        acc.z += f0b.x * w0 + f1b.x * w1;
        acc.w += f0b.y * w0 + f1b.y * w1;
    }
    for (; p < end; p++) {
        int n0 = csrc[p];
        float e0 = el[n0 * H + h] + erv;
        e0 = e0 > 0.f ? e0 : 0.2f * e0;
        float w0 = __expf(e0);
        uint2 u0 = __ldg(&ftu[n0 * 32 + lane]);
        s += w0;
        float2 f0a = __half22float2(*(__half2*)&u0.x);
        float2 f0b = __half22float2(*(__half2*)&u0.y);
        acc.x += f0a.x * w0;
        acc.y += f0a.y * w0;
        acc.z += f0b.x * w0;
        acc.w += f0b.y * w0;
    }

    float inv = (end > beg) ? 1.0f / s : 0.f;
    acc.x *= inv; acc.y *= inv; acc.z *= inv; acc.w *= inv;

    float4 xv = ((float4*)x)[node * 32 + lane];
    xv.x += acc.x > 0.f ? acc.x : expm1f(acc.x);
    xv.y += acc.y > 0.f ? acc.y : expm1f(acc.y);
    xv.z += acc.z > 0.f ? acc.z : expm1f(acc.z);
    xv.w += acc.w > 0.f ? acc.w : expm1f(acc.w);
    ((float4*)x)[node * 32 + lane] = xv;
}

// ---------------- fused edge MLP: warp-autonomous 16-edge tiles ----------------
__global__ void edge_mlp_tc(const int* __restrict__ src, const int* __restrict__ dst,
                            const uint2* __restrict__ p2, const uint2* __restrict__ q2,
                            const float* __restrict__ b1, const float* __restrict__ W2,
                            const float* __restrict__ b2, const float* __restrict__ W3,
                            const float* __restrict__ b3, float* __restrict__ out,
                            int E, int ntiles)
{
    extern __shared__ __half dsm[];
    // per-warp y1 slice: 16 rows x 136 halves; Bfrag after 8 warps' slices
    uint2* Bfrag = (uint2*)(dsm + 8 * 16 * 136);   // [8 kt][8 nt][32 lane]

    int t = threadIdx.x, lane = t & 31, warp = t >> 5;
    int tc = lane & 3, gr = lane >> 2;
    __half* Y = dsm + warp * 16 * 136;

    // pack W2[128,64] into fp16 fragments (once per block)
    for (int i = t; i < 8 * 8 * 32; i += 256) {
        int ln = i & 31, nt = (i >> 5) & 7, kt = i >> 8;
        int ltc = ln & 3, lgr = ln >> 2;
        int k0 = kt * 16, n = nt * 8 + lgr;
        __half2 h0 = __floats2half2_rn(W2[(k0 + 2 * ltc) * 64 + n],
                                       W2[(k0 + 2 * ltc + 1) * 64 + n]);
        __half2 h1 = __floats2half2_rn(W2[(k0 + 2 * ltc + 8) * 64 + n],
                                       W2[(k0 + 2 * ltc + 9) * 64 + n]);
        uint2 u;
        u.x = *(uint32_t*)&h0;
        u.y = *(uint32_t*)&h1;
        Bfrag[i] = u;
    }

    float4 b1v = ((const float4*)b1)[lane];
    float bc0[8], bc1[8];
    float w3r[8][2][2];
#pragma unroll
    for (int nt = 0; nt < 8; nt++) {
        int col = nt * 8 + tc * 2;
        bc0[nt] = b2[col];
        bc1[nt] = b2[col + 1];
        w3r[nt][0][0] = W3[col * 2];       w3r[nt][0][1] = W3[col * 2 + 1];
        w3r[nt][1][0] = W3[(col + 1) * 2]; w3r[nt][1][1] = W3[(col + 1) * 2 + 1];
    }
    float b30 = b3[0], b31 = b3[1];

    __syncthreads();

    int gw = blockIdx.x * 8 + warp;
    for (int g = gw; g < ntiles; g += gridDim.x * 8) {
        int ebase = g * 16;

#pragma unroll
        for (int i = 0; i < 16; i++) {
            int eid = ebase + i;
            float4 y = make_float4(0.f, 0.f, 0.f, 0.f);
            if (eid < E) {
                int s = __ldg(&src[eid]), d = __ldg(&dst[eid]);
                uint2 pv = __ldg(&p2[s * 32 + lane]);
                uint2 qv = __ldg(&q2[d * 32 + lane]);
                float2 pa = __half22float2(*(__half2*)&pv.x);
                float2 pb = __half22float2(*(__half2*)&pv.y);
                float2 qa = __half22float2(*(__half2*)&qv.x);
                float2 qb = __half22float2(*(__half2*)&qv.y);
                y.x = fmaxf(pa.x + qa.x + b1v.x, 0.f);
                y.y = fmaxf(pa.y + qa.y + b1v.y, 0.f);
                y.z = fmaxf(pb.x + qb.x + b1v.z, 0.f);
                y.w = fmaxf(pb.y + qb.y + b1v.w, 0.f);
            }
            __half2 h0 = __floats2half2_rn(y.x, y.y);
            __half2 h1 = __floats2half2_rn(y.z, y.w);
            uint2 u;
            u.x = *(uint32_t*)&h0;
            u.y = *(uint32_t*)&h1;
            *(uint2*)&Y[i * 136 + lane * 4] = u;
        }
        __syncwarp();

        float c[8][4];
#pragma unroll
        for (int nt = 0; nt < 8; nt++) {
            c[nt][0] = bc0[nt]; c[nt][1] = bc1[nt];
            c[nt][2] = bc0[nt]; c[nt][3] = bc1[nt];
        }
        const __half* Ar0 = Y + gr * 136;
        const __half* Ar1 = Ar0 + 8 * 136;
#pragma unroll
        for (int kt = 0; kt < 8; kt++) {
            int k0 = kt * 16;
            uint32_t a0 = *(const uint32_t*)&Ar0[k0 + 2 * tc];
            uint32_t a1 = *(const uint32_t*)&Ar1[k0 + 2 * tc];
            uint32_t a2 = *(const uint32_t*)&Ar0[k0 + 2 * tc + 8];
            uint32_t a3 = *(const uint32_t*)&Ar1[k0 + 2 * tc + 8];
            const uint2* bk = Bfrag + kt * 8 * 32 + lane;
#pragma unroll
            for (int nt = 0; nt < 8; nt++) {
                uint2 b = bk[nt * 32];
                mma_f16(c[nt][0], c[nt][1], c[nt][2], c[nt][3],
                        a0, a1, a2, a3, b.x, b.y);
            }
        }

        float pr00 = 0.f, pr01 = 0.f, pr10 = 0.f, pr11 = 0.f;
#pragma unroll
        for (int nt = 0; nt < 8; nt++) {
            float v0 = fmaxf(c[nt][0], 0.f);
            float v1 = fmaxf(c[nt][1], 0.f);
            float v2 = fmaxf(c[nt][2], 0.f);
            float v3 = fmaxf(c[nt][3], 0.f);
            pr00 += v0 * w3r[nt][0][0] + v1 * w3r[nt][1][0];
            pr01 += v0 * w3r[nt][0][1] + v1 * w3r[nt][1][1];
            pr10 += v2 * w3r[nt][0][0] + v3 * w3r[nt][1][0];
            pr11 += v2 * w3r[nt][0][1] + v3 * w3r[nt][1][1];
        }
#pragma unroll
        for (int off = 1; off <= 2; off <<= 1) {
            pr00 += __shfl_xor_sync(0xffffffffu, pr00, off);
            pr01 += __shfl_xor_sync(0xffffffffu, pr01, off);
            pr10 += __shfl_xor_sync(0xffffffffu, pr10, off);
            pr11 += __shfl_xor_sync(0xffffffffu, pr11, off);
        }
        if (tc == 0) {
            int e0 = ebase + gr, e1 = ebase + gr + 8;
            if (e0 < E) *(float2*)&out[e0 * 2] = make_float2(pr00 + b30, pr01 + b31);
            if (e1 < E) *(float2*)&out[e1 * 2] = make_float2(pr10 + b30, pr11 + b31);
        }
        __syncwarp();
    }
}

// ---------------- host launcher ----------------
extern "C" void kernel_launch(void* const* d_in, const int* in_sizes, int n_in,
                              void* d_out, int out_size)
{
    const float* h     = (const float*)d_in[0];
    const int*   src   = (const int*)d_in[1];
    const int*   dst   = (const int*)d_in[2];
    const float* W_emb = (const float*)d_in[3];
    const float* b_emb = (const float*)d_in[4];
    const float* W_g   = (const float*)d_in[5];
    const float* al_g  = (const float*)d_in[6];
    const float* ar_g  = (const float*)d_in[7];
    const float* W_l   = (const float*)d_in[8];
    const float* al_l  = (const float*)d_in[9];
    const float* ar_l  = (const float*)d_in[10];
    const float* W1    = (const float*)d_in[11];
    const float* b1    = (const float*)d_in[12];
    const float* W2    = (const float*)d_in[13];
    const float* b2    = (const float*)d_in[14];
    const float* W3    = (const float*)d_in[15];
    const float* b3    = (const float*)d_in[16];
    float* out = (float*)d_out;

    int NN = in_sizes[0] / 128;
    int NE = in_sizes[1];

    float *x, *el, *er;
    __half *ft, *p, *q;
    int *deg, *cur, *rowstart, *csrc;
    uint2* wpack;
    cudaGetSymbolAddress((void**)&x,   g_x);
    cudaGetSymbolAddress((void**)&ft,  g_ft);
    cudaGetSymbolAddress((void**)&el,  g_el);
    cudaGetSymbolAddress((void**)&er,  g_er);
    cudaGetSymbolAddress((void**)&p,   g_p);
    cudaGetSymbolAddress((void**)&q,   g_q);
    cudaGetSymbolAddress((void**)&deg, g_deg);
    cudaGetSymbolAddress((void**)&cur, g_cur);
    cudaGetSymbolAddress((void**)&rowstart, g_rowstart);
    cudaGetSymbolAddress((void**)&csrc, g_csrc);
    cudaGetSymbolAddress((void**)&wpack, g_wpack);

    const int FR = 8 * 16 * 32;   // uint2 per packed matrix

    pack_w16<<<16, 256>>>(W_emb,               wpack + 0 * FR);
    pack_w16<<<16, 256>>>(W_g,                 wpack + 1 * FR);
    pack_w16<<<16, 256>>>(W_g + 128 * 128,     wpack + 2 * FR);
    pack_w16<<<16, 256>>>(W_g + 2 * 128 * 128, wpack + 3 * FR);
    pack_w16<<<16, 256>>>(W_l,                 wpack + 4 * FR);
    pack_w16<<<16, 256>>>(W1,                  wpack + 5 * FR);
    pack_w16<<<16, 256>>>(W1 + 128 * 128,      wpack + 6 * FR);

    zero_int<<<(NN + 255) / 256, 256>>>(deg, NN);
    hist_dst<<<(NE + 255) / 256, 256>>>(dst, deg, NE);
    scan_deg<<<1, 1024>>>(deg, rowstart, cur, NN);
    scatter_csr<<<(NE + 255) / 256, 256>>>(src, dst, cur, csrc, NE);

    int gemm_blocks = (NN + 63) / 64;

    // embedding (fp32 out, no attn)
    gemm_f16<0, 0><<<gemm_blocks, 128>>>(h, wpack + 0 * FR, b_emb, x, nullptr,
                                         nullptr, nullptr, nullptr, nullptr, NN);

    // 4 GAT layers: GEMM (+fused el/er) then single-pass aggregate
    for (int L = 0; L < 4; L++) {
        const uint2* Wp = wpack + (size_t)(L + 1) * FR;
        if (L < 3) {
            gemm_f16<8, 1><<<gemm_blocks, 128>>>(x, Wp, nullptr, nullptr, (__half2*)ft,
                                                 al_g + (size_t)L * 128,
                                                 ar_g + (size_t)L * 128, el, er, NN);
            gat_aggregate<<<(NN * 32 + 255) / 256, 256>>>(rowstart, csrc, ft, el, er, x,
                                                          8, 4, NN);
        } else {
            gemm_f16<1, 1><<<gemm_blocks, 128>>>(x, Wp, nullptr, nullptr, (__half2*)ft,
                                                 al_l, ar_l, el, er, NN);
            gat_aggregate<<<(NN * 32 + 255) / 256, 256>>>(rowstart, csrc, ft, el, er, x,
                                                          1, 7, NN);
        }
    }

    // node-side halves of he@W1 (fp16 outputs)
    gemm_f16<0, 1><<<gemm_blocks, 128>>>(x, wpack + 5 * FR, nullptr, nullptr,
                                         (__half2*)p, nullptr, nullptr, nullptr, nullptr, NN);
    gemm_f16<0, 1><<<gemm_blocks, 128>>>(x, wpack + 6 * FR, nullptr, nullptr,
                                         (__half2*)q, nullptr, nullptr, nullptr, nullptr, NN);

    // fused edge MLP readout (warp-autonomous tiles)
    int ntiles = (NE + 15) / 16;
    size_t smem = 8 * 16 * 136 * sizeof(__half) + 8 * 8 * 32 * sizeof(uint2);
    cudaFuncSetAttribute(edge_mlp_tc, cudaFuncAttributeMaxDynamicSharedMemorySize,
                         (int)smem);
    edge_mlp_tc<<<1184, 256, smem>>>(src, dst, (const uint2*)p, (const uint2*)q,
                                     b1, W2, b2, W3, b3, out, NE, ntiles);
}

// round 7
// speedup vs baseline: 5.5874x; 1.2549x over previous
#include <cuda_runtime.h>
#include <cuda_bf16.h>
#include <cuda_fp16.h>
#include <math.h>
#include <stdint.h>

#define NMAX 50000
#define EMAX 1600000

// ---------------- scratch (static device globals; no allocation) ----------------
__device__ float  g_x[NMAX * 128];
__device__ __half g_ft[NMAX * 128];
__device__ float  g_el[NMAX * 8];
__device__ float  g_er[NMAX * 8];
__device__ __half g_p[NMAX * 128];
__device__ __half g_q[NMAX * 128];
__device__ int    g_deg[NMAX];
__device__ int    g_cur[NMAX];
__device__ int    g_rowstart[NMAX + 1];
__device__ int    g_csrc[EMAX];
__device__ uint2  g_wpack[7 * 8 * 16 * 32];   // 7 matrices, fp16 B-fragments

// ---------------- fp16 mma helper ----------------
__device__ __forceinline__ void mma_f16(float& c0, float& c1, float& c2, float& c3,
                                        uint32_t a0, uint32_t a1, uint32_t a2, uint32_t a3,
                                        uint32_t b0, uint32_t b1)
{
    asm volatile("mma.sync.aligned.m16n8k16.row.col.f32.f16.f16.f32 "
                 "{%0,%1,%2,%3}, {%4,%5,%6,%7}, {%8,%9}, {%0,%1,%2,%3};"
                 : "+f"(c0), "+f"(c1), "+f"(c2), "+f"(c3)
                 : "r"(a0), "r"(a1), "r"(a2), "r"(a3), "r"(b0), "r"(b1));
}

// ---------------- pack all 7 W[128,128] into fp16 B fragments (one launch) ----------------
__global__ void pack_w16_all(const float* __restrict__ W_emb, const float* __restrict__ W_g,
                             const float* __restrict__ W_l, const float* __restrict__ W1,
                             uint2* __restrict__ out)
{
    int m = blockIdx.y;
    const float* W;
    if (m == 0)      W = W_emb;
    else if (m < 4)  W = W_g + (size_t)(m - 1) * 128 * 128;
    else if (m == 4) W = W_l;
    else             W = W1 + (size_t)(m - 5) * 128 * 128;

    int i = blockIdx.x * 256 + threadIdx.x;        // 4096 per matrix
    int lane = i & 31, nt = (i >> 5) & 15, kt = i >> 9;
    int tc = lane & 3, gr = lane >> 2;
    int k0 = kt * 16, n = nt * 8 + gr;
    __half2 b0 = __floats2half2_rn(W[(k0 + 2 * tc) * 128 + n],
                                   W[(k0 + 2 * tc + 1) * 128 + n]);
    __half2 b1 = __floats2half2_rn(W[(k0 + 2 * tc + 8) * 128 + n],
                                   W[(k0 + 2 * tc + 9) * 128 + n]);
    uint2 u;
    u.x = *(uint32_t*)&b0;
    u.y = *(uint32_t*)&b1;
    out[(size_t)m * 4096 + i] = u;
}

// ---------------- fp16 GEMM + optional fused attention logits ----------------
// H=0: no attn. OUT=0: fp32 C; OUT=1: fp16 C. PQ=1: grid.y selects Bp half & out buf.
template<int H, int OUT, int PQ>
__global__ __launch_bounds__(128)
void gemm_f16(const float* __restrict__ A, const uint2* __restrict__ Bp,
              const float* __restrict__ bias, float* __restrict__ Cf,
              __half2* __restrict__ Ch, __half2* __restrict__ Ch2,
              const float* __restrict__ alp, const float* __restrict__ arp,
              float* __restrict__ el, float* __restrict__ er, int M)
{
    __shared__ __half As[64 * 136];
    __shared__ uint2  Bs[4096];
    int t = threadIdx.x, lane = t & 31, warp = t >> 5;
    int tc = lane & 3, gr = lane >> 2;
    int row0 = blockIdx.x * 64;

    if (PQ) {
        if (blockIdx.y == 1) { Bp += 4096; Ch = Ch2; }
    }

#pragma unroll
    for (int i = 0; i < 32; i++) Bs[t + i * 128] = __ldg(&Bp[t + i * 128]);

    const float4* A4 = (const float4*)A;
#pragma unroll
    for (int i = 0; i < 16; i++) {
        int f = t + i * 128;
        int r = f >> 5, c4 = f & 31;
        int grow = row0 + r;
        float4 v = (grow < M) ? A4[grow * 32 + c4] : make_float4(0.f, 0.f, 0.f, 0.f);
        __half2 h0 = __floats2half2_rn(v.x, v.y);
        __half2 h1 = __floats2half2_rn(v.z, v.w);
        uint2 u;
        u.x = *(uint32_t*)&h0;
        u.y = *(uint32_t*)&h1;
        *(uint2*)&As[r * 136 + c4 * 4] = u;
    }
    __syncthreads();

    float c[16][4];
#pragma unroll
    for (int nt = 0; nt < 16; nt++)
#pragma unroll
        for (int j = 0; j < 4; j++) c[nt][j] = 0.f;

    int m0 = warp * 16;
    const __half* Ar0 = As + (m0 + gr) * 136;
    const __half* Ar1 = Ar0 + 8 * 136;

#pragma unroll
    for (int kt = 0; kt < 8; kt++) {
        int k0 = kt * 16;
        uint32_t a0 = *(const uint32_t*)&Ar0[k0 + 2 * tc];
        uint32_t a1 = *(const uint32_t*)&Ar1[k0 + 2 * tc];
        uint32_t a2 = *(const uint32_t*)&Ar0[k0 + 2 * tc + 8];
        uint32_t a3 = *(const uint32_t*)&Ar1[k0 + 2 * tc + 8];
        const uint2* bk = Bs + kt * 16 * 32 + lane;
#pragma unroll
        for (int nt = 0; nt < 16; nt++) {
            uint2 b = bk[nt * 32];
            mma_f16(c[nt][0], c[nt][1], c[nt][2], c[nt][3],
                    a0, a1, a2, a3, b.x, b.y);
        }
    }

    int r0 = row0 + m0 + gr;
    int r1 = r0 + 8;

    if (H > 0) {
        constexpr int HH = (H > 0) ? H : 1;
        float el0[HH], er0[HH], el1[HH], er1[HH];
#pragma unroll
        for (int hh = 0; hh < HH; hh++) { el0[hh] = er0[hh] = el1[hh] = er1[hh] = 0.f; }
#pragma unroll
        for (int nt = 0; nt < 16; nt++) {
            int col = nt * 8 + tc * 2;
            int hh = (nt * H) >> 4;
            float a0 = __ldg(&alp[col]), a1 = __ldg(&alp[col + 1]);
            float g0 = __ldg(&arp[col]), g1 = __ldg(&arp[col + 1]);
            el0[hh] += c[nt][0] * a0 + c[nt][1] * a1;
            er0[hh] += c[nt][0] * g0 + c[nt][1] * g1;
            el1[hh] += c[nt][2] * a0 + c[nt][3] * a1;
            er1[hh] += c[nt][2] * g0 + c[nt][3] * g1;
        }
#pragma unroll
        for (int hh = 0; hh < HH; hh++) {
            el0[hh] += __shfl_xor_sync(0xffffffffu, el0[hh], 1);
            el0[hh] += __shfl_xor_sync(0xffffffffu, el0[hh], 2);
            er0[hh] += __shfl_xor_sync(0xffffffffu, er0[hh], 1);
            er0[hh] += __shfl_xor_sync(0xffffffffu, er0[hh], 2);
            el1[hh] += __shfl_xor_sync(0xffffffffu, el1[hh], 1);
            el1[hh] += __shfl_xor_sync(0xffffffffu, el1[hh], 2);
            er1[hh] += __shfl_xor_sync(0xffffffffu, er1[hh], 1);
            er1[hh] += __shfl_xor_sync(0xffffffffu, er1[hh], 2);
        }
        if (tc == 0) {
#pragma unroll
            for (int hh = 0; hh < HH; hh++) {
                if (r0 < M) { el[r0 * HH + hh] = el0[hh]; er[r0 * HH + hh] = er0[hh]; }
                if (r1 < M) { el[r1 * HH + hh] = el1[hh]; er[r1 * HH + hh] = er1[hh]; }
            }
        }
    }

#pragma unroll
    for (int nt = 0; nt < 16; nt++) {
        int col = nt * 8 + tc * 2;
        float b0 = 0.f, b1 = 0.f;
        if (bias) { b0 = __ldg(&bias[col]); b1 = __ldg(&bias[col + 1]); }
        float v00 = c[nt][0] + b0, v01 = c[nt][1] + b1;
        float v10 = c[nt][2] + b0, v11 = c[nt][3] + b1;
        if (OUT == 0) {
            if (r0 < M) *(float2*)&Cf[r0 * 128 + col] = make_float2(v00, v01);
            if (r1 < M) *(float2*)&Cf[r1 * 128 + col] = make_float2(v10, v11);
        } else {
            if (r0 < M) Ch[r0 * 64 + nt * 4 + tc] = __floats2half2_rn(v00, v01);
            if (r1 < M) Ch[r1 * 64 + nt * 4 + tc] = __floats2half2_rn(v10, v11);
        }
    }
}

// ---------------- CSR build ----------------
__global__ void zero_int(int* __restrict__ a, int n)
{
    int i = blockIdx.x * blockDim.x + threadIdx.x;
    if (i < n) a[i] = 0;
}

__global__ void hist_dst(const int* __restrict__ dst, int* __restrict__ deg, int E)
{
    int e = blockIdx.x * blockDim.x + threadIdx.x;
    if (e < E) atomicAdd(&deg[dst[e]], 1);
}

__global__ void scan_deg(const int* __restrict__ deg, int* __restrict__ rowstart,
                         int* __restrict__ cursor, int n)
{
    __shared__ int sums[1024];
    int t = threadIdx.x;
    int chunk = (n + 1023) / 1024;
    int beg = t * chunk;
    int end = beg + chunk < n ? beg + chunk : n;
    int s = 0;
    for (int i = beg; i < end; i++) s += deg[i];
    sums[t] = s;
    __syncthreads();
    for (int off = 1; off < 1024; off <<= 1) {
        int v = (t >= off) ? sums[t - off] : 0;
        __syncthreads();
        sums[t] += v;
        __syncthreads();
    }
    int excl = (t == 0) ? 0 : sums[t - 1];
    for (int i = beg; i < end; i++) {
        int d = deg[i];
        rowstart[i] = excl;
        cursor[i] = excl;
        excl += d;
    }
    if (t == 1023) rowstart[n] = sums[1023];
}

__global__ void scatter_csr(const int* __restrict__ src, const int* __restrict__ dst,
                            int* __restrict__ cur, int* __restrict__ csrc, int E)
{
    int e = blockIdx.x * blockDim.x + threadIdx.x;
    if (e >= E) return;
    int p = atomicAdd(&cur[dst[e]], 1);
    csrc[p] = src[e];
}

// ---------------- GAT aggregation: half-warp per edge, LDG.128, single pass ----------------
__global__ void gat_aggregate(const int* __restrict__ rowstart, const int* __restrict__ csrc,
                              const __half* __restrict__ ft, const float* __restrict__ el,
                              const float* __restrict__ er, float* __restrict__ x,
                              int H, int logDh, int NN)
{
    int node = (blockIdx.x * blockDim.x + threadIdx.x) >> 5;
    int lane = threadIdx.x & 31;
    if (node >= NN) return;
    int half = lane >> 4, sl = lane & 15;
    int h = (sl * 8) >> logDh;
    float erv = er[node * H + h];
    int beg = rowstart[node], end = rowstart[node + 1];
    int cnt = end - beg;
    int pairend = beg + (cnt & ~1);

    float s = 0.f;
    float acc[8];
#pragma unroll
    for (int j = 0; j < 8; j++) acc[j] = 0.f;
    const uint4* ft4 = (const uint4*)ft;

    int p = beg + half;
    // 2 pairs (4 edges) per warp-iteration
    for (; p + 2 < pairend; p += 4) {
        int n0 = __ldg(&csrc[p]);
        int n1 = __ldg(&csrc[p + 2]);
        float e0 = el[n0 * H + h] + erv;
        float e1 = el[n1 * H + h] + erv;
        e0 = e0 > 0.f ? e0 : 0.2f * e0;
        e1 = e1 > 0.f ? e1 : 0.2f * e1;
        float w0 = __expf(e0);
        float w1 = __expf(e1);
        uint4 u0 = __ldg(&ft4[n0 * 16 + sl]);
        uint4 u1 = __ldg(&ft4[n1 * 16 + sl]);
        s += w0 + w1;
        float2 f0 = __half22float2(*(__half2*)&u0.x);
        float2 f1 = __half22float2(*(__half2*)&u0.y);
        float2 f2 = __half22float2(*(__half2*)&u0.z);
        float2 f3 = __half22float2(*(__half2*)&u0.w);
        float2 g0 = __half22float2(*(__half2*)&u1.x);
        float2 g1 = __half22float2(*(__half2*)&u1.y);
        float2 g2 = __half22float2(*(__half2*)&u1.z);
        float2 g3 = __half22float2(*(__half2*)&u1.w);
        acc[0] += f0.x * w0 + g0.x * w1;
        acc[1] += f0.y * w0 + g0.y * w1;
        acc[2] += f1.x * w0 + g1.x * w1;
        acc[3] += f1.y * w0 + g1.y * w1;
        acc[4] += f2.x * w0 + g2.x * w1;
        acc[5] += f2.y * w0 + g2.y * w1;
        acc[6] += f3.x * w0 + g3.x * w1;
        acc[7] += f3.y * w0 + g3.y * w1;
    }
    if (p < pairend) {
        int n0 = __ldg(&csrc[p]);
        float e0 = el[n0 * H + h] + erv;
        e0 = e0 > 0.f ? e0 : 0.2f * e0;
        float w0 = __expf(e0);
        uint4 u0 = __ldg(&ft4[n0 * 16 + sl]);
        s += w0;
        float2 f0 = __half22float2(*(__half2*)&u0.x);
        float2 f1 = __half22float2(*(__half2*)&u0.y);
        float2 f2 = __half22float2(*(__half2*)&u0.z);
        float2 f3 = __half22float2(*(__half2*)&u0.w);
        acc[0] += f0.x * w0; acc[1] += f0.y * w0;
        acc[2] += f1.x * w0; acc[3] += f1.y * w0;
        acc[4] += f2.x * w0; acc[5] += f2.y * w0;
        acc[6] += f3.x * w0; acc[7] += f3.y * w0;
    }
    if ((cnt & 1) && half == 0) {
        int n0 = __ldg(&csrc[end - 1]);
        float e0 = el[n0 * H + h] + erv;
        e0 = e0 > 0.f ? e0 : 0.2f * e0;
        float w0 = __expf(e0);
        uint4 u0 = __ldg(&ft4[n0 * 16 + sl]);
        s += w0;
        float2 f0 = __half22float2(*(__half2*)&u0.x);
        float2 f1 = __half22float2(*(__half2*)&u0.y);
        float2 f2 = __half22float2(*(__half2*)&u0.z);
        float2 f3 = __half22float2(*(__half2*)&u0.w);
        acc[0] += f0.x * w0; acc[1] += f0.y * w0;
        acc[2] += f1.x * w0; acc[3] += f1.y * w0;
        acc[4] += f2.x * w0; acc[5] += f2.y * w0;
        acc[6] += f3.x * w0; acc[7] += f3.y * w0;
    }

    // combine halves
    s += __shfl_xor_sync(0xffffffffu, s, 16);
#pragma unroll
    for (int j = 0; j < 8; j++)
        acc[j] += __shfl_xor_sync(0xffffffffu, acc[j], 16);

    float inv = cnt ? 1.0f / s : 0.f;

    // x += elu(acc*inv); half 0 writes cols sl*8..+3, half 1 cols sl*8+4..+7
    int j0 = half * 4;
    float* xp = x + node * 128 + sl * 8 + half * 4;
    float4 xv = *(float4*)xp;
    float v0 = acc[j0] * inv, v1 = acc[j0 + 1] * inv;
    float v2 = acc[j0 + 2] * inv, v3 = acc[j0 + 3] * inv;
    xv.x += v0 > 0.f ? v0 : expm1f(v0);
    xv.y += v1 > 0.f ? v1 : expm1f(v1);
    xv.z += v2 > 0.f ? v2 : expm1f(v2);
    xv.w += v3 > 0.f ? v3 : expm1f(v3);
    *(float4*)xp = xv;
}

// ---------------- fused edge MLP: warp-autonomous 16-edge tiles, LDG.128 gather ----------------
__global__ void edge_mlp_tc(const int* __restrict__ src, const int* __restrict__ dst,
                            const uint4* __restrict__ p4, const uint4* __restrict__ q4,
                            const float* __restrict__ b1, const float* __restrict__ W2,
                            const float* __restrict__ b2, const float* __restrict__ W3,
                            const float* __restrict__ b3, float* __restrict__ out,
                            int E, int ntiles)
{
    extern __shared__ __half dsm[];
    uint2* Bfrag = (uint2*)(dsm + 8 * 16 * 136);   // [8 kt][8 nt][32 lane]

    int t = threadIdx.x, lane = t & 31, warp = t >> 5;
    int tc = lane & 3, gr = lane >> 2;
    int half = lane >> 4, sl = lane & 15;
    __half* Y = dsm + warp * 16 * 136;

    // pack W2[128,64] into fp16 fragments (once per block)
    for (int i = t; i < 8 * 8 * 32; i += 256) {
        int ln = i & 31, nt = (i >> 5) & 7, kt = i >> 8;
        int ltc = ln & 3, lgr = ln >> 2;
        int k0 = kt * 16, n = nt * 8 + lgr;
        __half2 h0 = __floats2half2_rn(W2[(k0 + 2 * ltc) * 64 + n],
                                       W2[(k0 + 2 * ltc + 1) * 64 + n]);
        __half2 h1 = __floats2half2_rn(W2[(k0 + 2 * ltc + 8) * 64 + n],
                                       W2[(k0 + 2 * ltc + 9) * 64 + n]);
        uint2 u;
        u.x = *(uint32_t*)&h0;
        u.y = *(uint32_t*)&h1;
        Bfrag[i] = u;
    }

    // b1 for cols sl*8..+7 as 4 half2
    __half2 b1h[4];
#pragma unroll
    for (int j = 0; j < 4; j++)
        b1h[j] = __floats2half2_rn(b1[sl * 8 + 2 * j], b1[sl * 8 + 2 * j + 1]);
    const __half2 zero2 = __floats2half2_rn(0.f, 0.f);

    float bc0[8], bc1[8];
    float w3r[8][2][2];
#pragma unroll
    for (int nt = 0; nt < 8; nt++) {
        int col = nt * 8 + tc * 2;
        bc0[nt] = b2[col];
        bc1[nt] = b2[col + 1];
        w3r[nt][0][0] = W3[col * 2];       w3r[nt][0][1] = W3[col * 2 + 1];
        w3r[nt][1][0] = W3[(col + 1) * 2]; w3r[nt][1][1] = W3[(col + 1) * 2 + 1];
    }
    float b30 = b3[0], b31 = b3[1];

    __syncthreads();

    int gw = blockIdx.x * 8 + warp;
    for (int g = gw; g < ntiles; g += gridDim.x * 8) {
        int ebase = g * 16;

        // gather: 2 edges per warp-iteration (half-warp per edge, 16B per lane)
#pragma unroll
        for (int i = 0; i < 16; i += 2) {
            int eid = ebase + i + half;
            uint4 yv = make_uint4(0u, 0u, 0u, 0u);
            if (eid < E) {
                int s = __ldg(&src[eid]), d = __ldg(&dst[eid]);
                uint4 pv = __ldg(&p4[s * 16 + sl]);
                uint4 qv = __ldg(&q4[d * 16 + sl]);
                __half2 y0 = __hmax2(__hadd2(__hadd2(*(__half2*)&pv.x, *(__half2*)&qv.x), b1h[0]), zero2);
                __half2 y1 = __hmax2(__hadd2(__hadd2(*(__half2*)&pv.y, *(__half2*)&qv.y), b1h[1]), zero2);
                __half2 y2 = __hmax2(__hadd2(__hadd2(*(__half2*)&pv.z, *(__half2*)&qv.z), b1h[2]), zero2);
                __half2 y3 = __hmax2(__hadd2(__hadd2(*(__half2*)&pv.w, *(__half2*)&qv.w), b1h[3]), zero2);
                yv.x = *(uint32_t*)&y0;
                yv.y = *(uint32_t*)&y1;
                yv.z = *(uint32_t*)&y2;
                yv.w = *(uint32_t*)&y3;
            }
            *(uint4*)&Y[(i + half) * 136 + sl * 8] = yv;
        }
        __syncwarp();

        float c[8][4];
#pragma unroll
        for (int nt = 0; nt < 8; nt++) {
            c[nt][0] = bc0[nt]; c[nt][1] = bc1[nt];
            c[nt][2] = bc0[nt]; c[nt][3] = bc1[nt];
        }
        const __half* Ar0 = Y + gr * 136;
        const __half* Ar1 = Ar0 + 8 * 136;
#pragma unroll
        for (int kt = 0; kt < 8; kt++) {
            int k0 = kt * 16;
            uint32_t a0 = *(const uint32_t*)&Ar0[k0 + 2 * tc];
            uint32_t a1 = *(const uint32_t*)&Ar1[k0 + 2 * tc];
            uint32_t a2 = *(const uint32_t*)&Ar0[k0 + 2 * tc + 8];
            uint32_t a3 = *(const uint32_t*)&Ar1[k0 + 2 * tc + 8];
            const uint2* bk = Bfrag + kt * 8 * 32 + lane;
#pragma unroll
            for (int nt = 0; nt < 8; nt++) {
                uint2 b = bk[nt * 32];
                mma_f16(c[nt][0], c[nt][1], c[nt][2], c[nt][3],
                        a0, a1, a2, a3, b.x, b.y);
            }
        }

        float pr00 = 0.f, pr01 = 0.f, pr10 = 0.f, pr11 = 0.f;
#pragma unroll
        for (int nt = 0; nt < 8; nt++) {
            float v0 = fmaxf(c[nt][0], 0.f);
            float v1 = fmaxf(c[nt][1], 0.f);
            float v2 = fmaxf(c[nt][2], 0.f);
            float v3 = fmaxf(c[nt][3], 0.f);
            pr00 += v0 * w3r[nt][0][0] + v1 * w3r[nt][1][0];
            pr01 += v0 * w3r[nt][0][1] + v1 * w3r[nt][1][1];
            pr10 += v2 * w3r[nt][0][0] + v3 * w3r[nt][1][0];
            pr11 += v2 * w3r[nt][0][1] + v3 * w3r[nt][1][1];
        }
#pragma unroll
        for (int off = 1; off <= 2; off <<= 1) {
            pr00 += __shfl_xor_sync(0xffffffffu, pr00, off);
            pr01 += __shfl_xor_sync(0xffffffffu, pr01, off);
            pr10 += __shfl_xor_sync(0xffffffffu, pr10, off);
            pr11 += __shfl_xor_sync(0xffffffffu, pr11, off);
        }
        if (tc == 0) {
            int e0 = ebase + gr, e1 = ebase + gr + 8;
            if (e0 < E) *(float2*)&out[e0 * 2] = make_float2(pr00 + b30, pr01 + b31);
            if (e1 < E) *(float2*)&out[e1 * 2] = make_float2(pr10 + b30, pr11 + b31);
        }
        __syncwarp();
    }
}

// ---------------- host launcher ----------------
extern "C" void kernel_launch(void* const* d_in, const int* in_sizes, int n_in,
                              void* d_out, int out_size)
{
    const float* h     = (const float*)d_in[0];
    const int*   src   = (const int*)d_in[1];
    const int*   dst   = (const int*)d_in[2];
    const float* W_emb = (const float*)d_in[3];
    const float* b_emb = (const float*)d_in[4];
    const float* W_g   = (const float*)d_in[5];
    const float* al_g  = (const float*)d_in[6];
    const float* ar_g  = (const float*)d_in[7];
    const float* W_l   = (const float*)d_in[8];
    const float* al_l  = (const float*)d_in[9];
    const float* ar_l  = (const float*)d_in[10];
    const float* W1    = (const float*)d_in[11];
    const float* b1    = (const float*)d_in[12];
    const float* W2    = (const float*)d_in[13];
    const float* b2    = (const float*)d_in[14];
    const float* W3    = (const float*)d_in[15];
    const float* b3    = (const float*)d_in[16];
    float* out = (float*)d_out;

    int NN = in_sizes[0] / 128;
    int NE = in_sizes[1];

    float *x, *el, *er;
    __half *ft, *p, *q;
    int *deg, *cur, *rowstart, *csrc;
    uint2* wpack;
    cudaGetSymbolAddress((void**)&x,   g_x);
    cudaGetSymbolAddress((void**)&ft,  g_ft);
    cudaGetSymbolAddress((void**)&el,  g_el);
    cudaGetSymbolAddress((void**)&er,  g_er);
    cudaGetSymbolAddress((void**)&p,   g_p);
    cudaGetSymbolAddress((void**)&q,   g_q);
    cudaGetSymbolAddress((void**)&deg, g_deg);
    cudaGetSymbolAddress((void**)&cur, g_cur);
    cudaGetSymbolAddress((void**)&rowstart, g_rowstart);
    cudaGetSymbolAddress((void**)&csrc, g_csrc);
    cudaGetSymbolAddress((void**)&wpack, g_wpack);

    const int FR = 8 * 16 * 32;   // uint2 per packed matrix

    // pack all 7 weight matrices (one launch)
    pack_w16_all<<<dim3(16, 7), 256>>>(W_emb, W_g, W_l, W1, wpack);

    // CSR build (by dst)
    zero_int<<<(NN + 255) / 256, 256>>>(deg, NN);
    hist_dst<<<(NE + 255) / 256, 256>>>(dst, deg, NE);
    scan_deg<<<1, 1024>>>(deg, rowstart, cur, NN);
    scatter_csr<<<(NE + 255) / 256, 256>>>(src, dst, cur, csrc, NE);

    int gemm_blocks = (NN + 63) / 64;

    // embedding (fp32 out, no attn)
    gemm_f16<0, 0, 0><<<gemm_blocks, 128>>>(h, wpack + 0 * FR, b_emb, x, nullptr, nullptr,
                                            nullptr, nullptr, nullptr, nullptr, NN);

    // 4 GAT layers
    for (int L = 0; L < 4; L++) {
        const uint2* Wp = wpack + (size_t)(L + 1) * FR;
        if (L < 3) {
            gemm_f16<8, 1, 0><<<gemm_blocks, 128>>>(x, Wp, nullptr, nullptr, (__half2*)ft,
                                                    nullptr, al_g + (size_t)L * 128,
                                                    ar_g + (size_t)L * 128, el, er, NN);
            gat_aggregate<<<(NN * 32 + 255) / 256, 256>>>(rowstart, csrc, ft, el, er, x,
                                                          8, 4, NN);
        } else {
            gemm_f16<1, 1, 0><<<gemm_blocks, 128>>>(x, Wp, nullptr, nullptr, (__half2*)ft,
                                                    nullptr, al_l, ar_l, el, er, NN);
            gat_aggregate<<<(NN * 32 + 255) / 256, 256>>>(rowstart, csrc, ft, el, er, x,
                                                          1, 7, NN);
        }
    }

    // p and q in ONE launch (grid.y selects half of W1)
    gemm_f16<0, 1, 1><<<dim3(gemm_blocks, 2), 128>>>(x, wpack + 5 * FR, nullptr, nullptr,
                                                     (__half2*)p, (__half2*)q,
                                                     nullptr, nullptr, nullptr, nullptr, NN);

    // fused edge MLP readout
    int ntiles = (NE + 15) / 16;
    size_t smem = 8 * 16 * 136 * sizeof(__half) + 8 * 8 * 32 * sizeof(uint2);
    cudaFuncSetAttribute(edge_mlp_tc, cudaFuncAttributeMaxDynamicSharedMemorySize,
                         (int)smem);
    edge_mlp_tc<<<1184, 256, smem>>>(src, dst, (const uint4*)p, (const uint4*)q,
                                     b1, W2, b2, W3, b3, out, NE, ntiles);
}

// round 8
// speedup vs baseline: 6.2374x; 1.1163x over previous
#include <cuda_runtime.h>
#include <cuda_bf16.h>
#include <cuda_fp16.h>
#include <math.h>
#include <stdint.h>

#define NMAX 50000
#define EMAX 1600000

// ---------------- scratch (static device globals; no allocation) ----------------
__device__ float  g_x[NMAX * 128];
__device__ __half g_ft[NMAX * 128];
__device__ float  g_el[NMAX * 8];
__device__ float  g_er[NMAX * 8];
__device__ __half g_p[NMAX * 128];
__device__ __half g_q[NMAX * 128];
__device__ int    g_deg[NMAX];
__device__ int    g_cur[NMAX];
__device__ int    g_rowstart[NMAX + 1];
__device__ int    g_csrc[EMAX];
__device__ int    g_bsum[256];
__device__ int    g_boff[256];
__device__ uint2  g_wpack[7 * 8 * 16 * 32];   // 7 matrices, fp16 B-fragments

// ---------------- fp16 mma helper ----------------
__device__ __forceinline__ void mma_f16(float& c0, float& c1, float& c2, float& c3,
                                        uint32_t a0, uint32_t a1, uint32_t a2, uint32_t a3,
                                        uint32_t b0, uint32_t b1)
{
    asm volatile("mma.sync.aligned.m16n8k16.row.col.f32.f16.f16.f32 "
                 "{%0,%1,%2,%3}, {%4,%5,%6,%7}, {%8,%9}, {%0,%1,%2,%3};"
                 : "+f"(c0), "+f"(c1), "+f"(c2), "+f"(c3)
                 : "r"(a0), "r"(a1), "r"(a2), "r"(a3), "r"(b0), "r"(b1));
}

// ---------------- pack all 7 W[128,128] into fp16 B fragments (one launch) ----------------
__global__ void pack_w16_all(const float* __restrict__ W_emb, const float* __restrict__ W_g,
                             const float* __restrict__ W_l, const float* __restrict__ W1,
                             uint2* __restrict__ out)
{
    int m = blockIdx.y;
    const float* W;
    if (m == 0)      W = W_emb;
    else if (m < 4)  W = W_g + (size_t)(m - 1) * 128 * 128;
    else if (m == 4) W = W_l;
    else             W = W1 + (size_t)(m - 5) * 128 * 128;

    int i = blockIdx.x * 256 + threadIdx.x;        // 4096 per matrix
    int lane = i & 31, nt = (i >> 5) & 15, kt = i >> 9;
    int tc = lane & 3, gr = lane >> 2;
    int k0 = kt * 16, n = nt * 8 + gr;
    __half2 b0 = __floats2half2_rn(W[(k0 + 2 * tc) * 128 + n],
                                   W[(k0 + 2 * tc + 1) * 128 + n]);
    __half2 b1 = __floats2half2_rn(W[(k0 + 2 * tc + 8) * 128 + n],
                                   W[(k0 + 2 * tc + 9) * 128 + n]);
    uint2 u;
    u.x = *(uint32_t*)&b0;
    u.y = *(uint32_t*)&b1;
    out[(size_t)m * 4096 + i] = u;
}

// ---------------- fp16 GEMM + optional fused attention logits ----------------
template<int H, int OUT, int PQ>
__global__ __launch_bounds__(128)
void gemm_f16(const float* __restrict__ A, const uint2* __restrict__ Bp,
              const float* __restrict__ bias, float* __restrict__ Cf,
              __half2* __restrict__ Ch, __half2* __restrict__ Ch2,
              const float* __restrict__ alp, const float* __restrict__ arp,
              float* __restrict__ el, float* __restrict__ er, int M)
{
    __shared__ __half As[64 * 136];
    __shared__ uint2  Bs[4096];
    int t = threadIdx.x, lane = t & 31, warp = t >> 5;
    int tc = lane & 3, gr = lane >> 2;
    int row0 = blockIdx.x * 64;

    if (PQ) {
        if (blockIdx.y == 1) { Bp += 4096; Ch = Ch2; }
    }

#pragma unroll
    for (int i = 0; i < 32; i++) Bs[t + i * 128] = __ldg(&Bp[t + i * 128]);

    const float4* A4 = (const float4*)A;
#pragma unroll
    for (int i = 0; i < 16; i++) {
        int f = t + i * 128;
        int r = f >> 5, c4 = f & 31;
        int grow = row0 + r;
        float4 v = (grow < M) ? A4[grow * 32 + c4] : make_float4(0.f, 0.f, 0.f, 0.f);
        __half2 h0 = __floats2half2_rn(v.x, v.y);
        __half2 h1 = __floats2half2_rn(v.z, v.w);
        uint2 u;
        u.x = *(uint32_t*)&h0;
        u.y = *(uint32_t*)&h1;
        *(uint2*)&As[r * 136 + c4 * 4] = u;
    }
    __syncthreads();

    float c[16][4];
#pragma unroll
    for (int nt = 0; nt < 16; nt++)
#pragma unroll
        for (int j = 0; j < 4; j++) c[nt][j] = 0.f;

    int m0 = warp * 16;
    const __half* Ar0 = As + (m0 + gr) * 136;
    const __half* Ar1 = Ar0 + 8 * 136;

#pragma unroll
    for (int kt = 0; kt < 8; kt++) {
        int k0 = kt * 16;
        uint32_t a0 = *(const uint32_t*)&Ar0[k0 + 2 * tc];
        uint32_t a1 = *(const uint32_t*)&Ar1[k0 + 2 * tc];
        uint32_t a2 = *(const uint32_t*)&Ar0[k0 + 2 * tc + 8];
        uint32_t a3 = *(const uint32_t*)&Ar1[k0 + 2 * tc + 8];
        const uint2* bk = Bs + kt * 16 * 32 + lane;
#pragma unroll
        for (int nt = 0; nt < 16; nt++) {
            uint2 b = bk[nt * 32];
            mma_f16(c[nt][0], c[nt][1], c[nt][2], c[nt][3],
                    a0, a1, a2, a3, b.x, b.y);
        }
    }

    int r0 = row0 + m0 + gr;
    int r1 = r0 + 8;

    if (H > 0) {
        constexpr int HH = (H > 0) ? H : 1;
        float el0[HH], er0[HH], el1[HH], er1[HH];
#pragma unroll
        for (int hh = 0; hh < HH; hh++) { el0[hh] = er0[hh] = el1[hh] = er1[hh] = 0.f; }
#pragma unroll
        for (int nt = 0; nt < 16; nt++) {
            int col = nt * 8 + tc * 2;
            int hh = (nt * H) >> 4;
            float a0 = __ldg(&alp[col]), a1 = __ldg(&alp[col + 1]);
            float g0 = __ldg(&arp[col]), g1 = __ldg(&arp[col + 1]);
            el0[hh] += c[nt][0] * a0 + c[nt][1] * a1;
            er0[hh] += c[nt][0] * g0 + c[nt][1] * g1;
            el1[hh] += c[nt][2] * a0 + c[nt][3] * a1;
            er1[hh] += c[nt][2] * g0 + c[nt][3] * g1;
        }
#pragma unroll
        for (int hh = 0; hh < HH; hh++) {
            el0[hh] += __shfl_xor_sync(0xffffffffu, el0[hh], 1);
            el0[hh] += __shfl_xor_sync(0xffffffffu, el0[hh], 2);
            er0[hh] += __shfl_xor_sync(0xffffffffu, er0[hh], 1);
            er0[hh] += __shfl_xor_sync(0xffffffffu, er0[hh], 2);
            el1[hh] += __shfl_xor_sync(0xffffffffu, el1[hh], 1);
            el1[hh] += __shfl_xor_sync(0xffffffffu, el1[hh], 2);
            er1[hh] += __shfl_xor_sync(0xffffffffu, er1[hh], 1);
            er1[hh] += __shfl_xor_sync(0xffffffffu, er1[hh], 2);
        }
        if (tc == 0) {
#pragma unroll
            for (int hh = 0; hh < HH; hh++) {
                if (r0 < M) { el[r0 * HH + hh] = el0[hh]; er[r0 * HH + hh] = er0[hh]; }
                if (r1 < M) { el[r1 * HH + hh] = el1[hh]; er[r1 * HH + hh] = er1[hh]; }
            }
        }
    }

#pragma unroll
    for (int nt = 0; nt < 16; nt++) {
        int col = nt * 8 + tc * 2;
        float b0 = 0.f, b1 = 0.f;
        if (bias) { b0 = __ldg(&bias[col]); b1 = __ldg(&bias[col + 1]); }
        float v00 = c[nt][0] + b0, v01 = c[nt][1] + b1;
        float v10 = c[nt][2] + b0, v11 = c[nt][3] + b1;
        if (OUT == 0) {
            if (r0 < M) *(float2*)&Cf[r0 * 128 + col] = make_float2(v00, v01);
            if (r1 < M) *(float2*)&Cf[r1 * 128 + col] = make_float2(v10, v11);
        } else {
            if (r0 < M) Ch[r0 * 64 + nt * 4 + tc] = __floats2half2_rn(v00, v01);
            if (r1 < M) Ch[r1 * 64 + nt * 4 + tc] = __floats2half2_rn(v10, v11);
        }
    }
}

// ---------------- CSR build (parallel) ----------------
__global__ void zero_int(int* __restrict__ a, int n)
{
    int i = blockIdx.x * blockDim.x + threadIdx.x;
    if (i < n) a[i] = 0;
}

// 4 edges per thread
__global__ void hist_dst(const int* __restrict__ dst, int* __restrict__ deg, int E)
{
    int base = (blockIdx.x * blockDim.x + threadIdx.x) * 4;
    if (base + 3 < E) {
        int4 d = *(const int4*)(dst + base);
        atomicAdd(&deg[d.x], 1);
        atomicAdd(&deg[d.y], 1);
        atomicAdd(&deg[d.z], 1);
        atomicAdd(&deg[d.w], 1);
    } else {
        for (int e = base; e < E; e++) atomicAdd(&deg[dst[e]], 1);
    }
}

// phase 1: per-block sums of 256-entry chunks
__global__ void scan_p1(const int* __restrict__ deg, int* __restrict__ bsum, int n)
{
    __shared__ int sh[256];
    int i = blockIdx.x * 256 + threadIdx.x;
    int v = (i < n) ? deg[i] : 0;
    sh[threadIdx.x] = v;
    __syncthreads();
#pragma unroll
    for (int off = 128; off > 0; off >>= 1) {
        if (threadIdx.x < off) sh[threadIdx.x] += sh[threadIdx.x + off];
        __syncthreads();
    }
    if (threadIdx.x == 0) bsum[blockIdx.x] = sh[0];
}

// phase 2: single small block scans the partials (exclusive)
__global__ void scan_p2(const int* __restrict__ bsum, int* __restrict__ boff, int nb)
{
    __shared__ int sh[256];
    int t = threadIdx.x;
    int v = (t < nb) ? bsum[t] : 0;
    sh[t] = v;
    __syncthreads();
#pragma unroll
    for (int off = 1; off < 256; off <<= 1) {
        int u = (t >= off) ? sh[t - off] : 0;
        __syncthreads();
        sh[t] += u;
        __syncthreads();
    }
    if (t < nb) boff[t] = sh[t] - v;   // exclusive
}

// phase 3: local exclusive scan + block offset -> rowstart, cur
__global__ void scan_p3(const int* __restrict__ deg, const int* __restrict__ boff,
                        int* __restrict__ rowstart, int* __restrict__ cur, int n, int E)
{
    __shared__ int sh[256];
    int t = threadIdx.x;
    int i = blockIdx.x * 256 + t;
    int v = (i < n) ? deg[i] : 0;
    sh[t] = v;
    __syncthreads();
#pragma unroll
    for (int off = 1; off < 256; off <<= 1) {
        int u = (t >= off) ? sh[t - off] : 0;
        __syncthreads();
        sh[t] += u;
        __syncthreads();
    }
    if (i < n) {
        int r = boff[blockIdx.x] + sh[t] - v;   // exclusive
        rowstart[i] = r;
        cur[i] = r;
    }
    if (i == 0) rowstart[n] = E;
}

// 4 edges per thread
__global__ void scatter_csr(const int* __restrict__ src, const int* __restrict__ dst,
                            int* __restrict__ cur, int* __restrict__ csrc, int E)
{
    int base = (blockIdx.x * blockDim.x + threadIdx.x) * 4;
    if (base + 3 < E) {
        int4 d = *(const int4*)(dst + base);
        int4 s = *(const int4*)(src + base);
        csrc[atomicAdd(&cur[d.x], 1)] = s.x;
        csrc[atomicAdd(&cur[d.y], 1)] = s.y;
        csrc[atomicAdd(&cur[d.z], 1)] = s.z;
        csrc[atomicAdd(&cur[d.w], 1)] = s.w;
    } else {
        for (int e = base; e < E; e++)
            csrc[atomicAdd(&cur[dst[e]], 1)] = src[e];
    }
}

// ---------------- GAT aggregation: half-warp per edge, LDG.128, single pass ----------------
__global__ void gat_aggregate(const int* __restrict__ rowstart, const int* __restrict__ csrc,
                              const __half* __restrict__ ft, const float* __restrict__ el,
                              const float* __restrict__ er, float* __restrict__ x,
                              int H, int logDh, int NN)
{
    int node = (blockIdx.x * blockDim.x + threadIdx.x) >> 5;
    int lane = threadIdx.x & 31;
    if (node >= NN) return;
    int half = lane >> 4, sl = lane & 15;
    int h = (sl * 8) >> logDh;
    float erv = er[node * H + h];
    int beg = rowstart[node], end = rowstart[node + 1];
    int cnt = end - beg;
    int pairend = beg + (cnt & ~1);

    float s = 0.f;
    float acc[8];
#pragma unroll
    for (int j = 0; j < 8; j++) acc[j] = 0.f;
    const uint4* ft4 = (const uint4*)ft;

    int p = beg + half;
    for (; p + 2 < pairend; p += 4) {
        int n0 = __ldg(&csrc[p]);
        int n1 = __ldg(&csrc[p + 2]);
        float e0 = el[n0 * H + h] + erv;
        float e1 = el[n1 * H + h] + erv;
        e0 = e0 > 0.f ? e0 : 0.2f * e0;
        e1 = e1 > 0.f ? e1 : 0.2f * e1;
        float w0 = __expf(e0);
        float w1 = __expf(e1);
        uint4 u0 = __ldg(&ft4[n0 * 16 + sl]);
        uint4 u1 = __ldg(&ft4[n1 * 16 + sl]);
        s += w0 + w1;
        float2 f0 = __half22float2(*(__half2*)&u0.x);
        float2 f1 = __half22float2(*(__half2*)&u0.y);
        float2 f2 = __half22float2(*(__half2*)&u0.z);
        float2 f3 = __half22float2(*(__half2*)&u0.w);
        float2 g0 = __half22float2(*(__half2*)&u1.x);
        float2 g1 = __half22float2(*(__half2*)&u1.y);
        float2 g2 = __half22float2(*(__half2*)&u1.z);
        float2 g3 = __half22float2(*(__half2*)&u1.w);
        acc[0] += f0.x * w0 + g0.x * w1;
        acc[1] += f0.y * w0 + g0.y * w1;
        acc[2] += f1.x * w0 + g1.x * w1;
        acc[3] += f1.y * w0 + g1.y * w1;
        acc[4] += f2.x * w0 + g2.x * w1;
        acc[5] += f2.y * w0 + g2.y * w1;
        acc[6] += f3.x * w0 + g3.x * w1;
        acc[7] += f3.y * w0 + g3.y * w1;
    }
    if (p < pairend) {
        int n0 = __ldg(&csrc[p]);
        float e0 = el[n0 * H + h] + erv;
        e0 = e0 > 0.f ? e0 : 0.2f * e0;
        float w0 = __expf(e0);
        uint4 u0 = __ldg(&ft4[n0 * 16 + sl]);
        s += w0;
        float2 f0 = __half22float2(*(__half2*)&u0.x);
        float2 f1 = __half22float2(*(__half2*)&u0.y);
        float2 f2 = __half22float2(*(__half2*)&u0.z);
        float2 f3 = __half22float2(*(__half2*)&u0.w);
        acc[0] += f0.x * w0; acc[1] += f0.y * w0;
        acc[2] += f1.x * w0; acc[3] += f1.y * w0;
        acc[4] += f2.x * w0; acc[5] += f2.y * w0;
        acc[6] += f3.x * w0; acc[7] += f3.y * w0;
    }
    if ((cnt & 1) && half == 0) {
        int n0 = __ldg(&csrc[end - 1]);
        float e0 = el[n0 * H + h] + erv;
        e0 = e0 > 0.f ? e0 : 0.2f * e0;
        float w0 = __expf(e0);
        uint4 u0 = __ldg(&ft4[n0 * 16 + sl]);
        s += w0;
        float2 f0 = __half22float2(*(__half2*)&u0.x);
        float2 f1 = __half22float2(*(__half2*)&u0.y);
        float2 f2 = __half22float2(*(__half2*)&u0.z);
        float2 f3 = __half22float2(*(__half2*)&u0.w);
        acc[0] += f0.x * w0; acc[1] += f0.y * w0;
        acc[2] += f1.x * w0; acc[3] += f1.y * w0;
        acc[4] += f2.x * w0; acc[5] += f2.y * w0;
        acc[6] += f3.x * w0; acc[7] += f3.y * w0;
    }

    s += __shfl_xor_sync(0xffffffffu, s, 16);
#pragma unroll
    for (int j = 0; j < 8; j++)
        acc[j] += __shfl_xor_sync(0xffffffffu, acc[j], 16);

    float inv = cnt ? 1.0f / s : 0.f;

    int j0 = half * 4;
    float* xp = x + node * 128 + sl * 8 + half * 4;
    float4 xv = *(float4*)xp;
    float v0 = acc[j0] * inv, v1 = acc[j0 + 1] * inv;
    float v2 = acc[j0 + 2] * inv, v3 = acc[j0 + 3] * inv;
    xv.x += v0 > 0.f ? v0 : expm1f(v0);
    xv.y += v1 > 0.f ? v1 : expm1f(v1);
    xv.z += v2 > 0.f ? v2 : expm1f(v2);
    xv.w += v3 > 0.f ? v3 : expm1f(v3);
    *(float4*)xp = xv;
}

// ---------------- fused edge MLP: warp-autonomous 16-edge tiles, LDG.128 gather ----------------
__global__ void edge_mlp_tc(const int* __restrict__ src, const int* __restrict__ dst,
                            const uint4* __restrict__ p4, const uint4* __restrict__ q4,
                            const float* __restrict__ b1, const float* __restrict__ W2,
                            const float* __restrict__ b2, const float* __restrict__ W3,
                            const float* __restrict__ b3, float* __restrict__ out,
                            int E, int ntiles)
{
    extern __shared__ __half dsm[];
    uint2* Bfrag = (uint2*)(dsm + 8 * 16 * 136);   // [8 kt][8 nt][32 lane]

    int t = threadIdx.x, lane = t & 31, warp = t >> 5;
    int tc = lane & 3, gr = lane >> 2;
    int half = lane >> 4, sl = lane & 15;
    __half* Y = dsm + warp * 16 * 136;

    for (int i = t; i < 8 * 8 * 32; i += 256) {
        int ln = i & 31, nt = (i >> 5) & 7, kt = i >> 8;
        int ltc = ln & 3, lgr = ln >> 2;
        int k0 = kt * 16, n = nt * 8 + lgr;
        __half2 h0 = __floats2half2_rn(W2[(k0 + 2 * ltc) * 64 + n],
                                       W2[(k0 + 2 * ltc + 1) * 64 + n]);
        __half2 h1 = __floats2half2_rn(W2[(k0 + 2 * ltc + 8) * 64 + n],
                                       W2[(k0 + 2 * ltc + 9) * 64 + n]);
        uint2 u;
        u.x = *(uint32_t*)&h0;
        u.y = *(uint32_t*)&h1;
        Bfrag[i] = u;
    }

    __half2 b1h[4];
#pragma unroll
    for (int j = 0; j < 4; j++)
        b1h[j] = __floats2half2_rn(b1[sl * 8 + 2 * j], b1[sl * 8 + 2 * j + 1]);
    const __half2 zero2 = __floats2half2_rn(0.f, 0.f);

    float bc0[8], bc1[8];
    float w3r[8][2][2];
#pragma unroll
    for (int nt = 0; nt < 8; nt++) {
        int col = nt * 8 + tc * 2;
        bc0[nt] = b2[col];
        bc1[nt] = b2[col + 1];
        w3r[nt][0][0] = W3[col * 2];       w3r[nt][0][1] = W3[col * 2 + 1];
        w3r[nt][1][0] = W3[(col + 1) * 2]; w3r[nt][1][1] = W3[(col + 1) * 2 + 1];
    }
    float b30 = b3[0], b31 = b3[1];

    __syncthreads();

    int gw = blockIdx.x * 8 + warp;
    for (int g = gw; g < ntiles; g += gridDim.x * 8) {
        int ebase = g * 16;

#pragma unroll
        for (int i = 0; i < 16; i += 2) {
            int eid = ebase + i + half;
            uint4 yv = make_uint4(0u, 0u, 0u, 0u);
            if (eid < E) {
                int s = __ldg(&src[eid]), d = __ldg(&dst[eid]);
                uint4 pv = __ldg(&p4[s * 16 + sl]);
                uint4 qv = __ldg(&q4[d * 16 + sl]);
                __half2 y0 = __hmax2(__hadd2(__hadd2(*(__half2*)&pv.x, *(__half2*)&qv.x), b1h[0]), zero2);
                __half2 y1 = __hmax2(__hadd2(__hadd2(*(__half2*)&pv.y, *(__half2*)&qv.y), b1h[1]), zero2);
                __half2 y2 = __hmax2(__hadd2(__hadd2(*(__half2*)&pv.z, *(__half2*)&qv.z), b1h[2]), zero2);
                __half2 y3 = __hmax2(__hadd2(__hadd2(*(__half2*)&pv.w, *(__half2*)&qv.w), b1h[3]), zero2);
                yv.x = *(uint32_t*)&y0;
                yv.y = *(uint32_t*)&y1;
                yv.z = *(uint32_t*)&y2;
                yv.w = *(uint32_t*)&y3;
            }
            *(uint4*)&Y[(i + half) * 136 + sl * 8] = yv;
        }
        __syncwarp();

        float c[8][4];
#pragma unroll
        for (int nt = 0; nt < 8; nt++) {
            c[nt][0] = bc0[nt]; c[nt][1] = bc1[nt];
            c[nt][2] = bc0[nt]; c[nt][3] = bc1[nt];
        }
        const __half* Ar0 = Y + gr * 136;
        const __half* Ar1 = Ar0 + 8 * 136;
#pragma unroll
        for (int kt = 0; kt < 8; kt++) {
            int k0 = kt * 16;
            uint32_t a0 = *(const uint32_t*)&Ar0[k0 + 2 * tc];
            uint32_t a1 = *(const uint32_t*)&Ar1[k0 + 2 * tc];
            uint32_t a2 = *(const uint32_t*)&Ar0[k0 + 2 * tc + 8];
            uint32_t a3 = *(const uint32_t*)&Ar1[k0 + 2 * tc + 8];
            const uint2* bk = Bfrag + kt * 8 * 32 + lane;
#pragma unroll
            for (int nt = 0; nt < 8; nt++) {
                uint2 b = bk[nt * 32];
                mma_f16(c[nt][0], c[nt][1], c[nt][2], c[nt][3],
                        a0, a1, a2, a3, b.x, b.y);
            }
        }

        float pr00 = 0.f, pr01 = 0.f, pr10 = 0.f, pr11 = 0.f;
#pragma unroll
        for (int nt = 0; nt < 8; nt++) {
            float v0 = fmaxf(c[nt][0], 0.f);
            float v1 = fmaxf(c[nt][1], 0.f);
            float v2 = fmaxf(c[nt][2], 0.f);
            float v3 = fmaxf(c[nt][3], 0.f);
            pr00 += v0 * w3r[nt][0][0] + v1 * w3r[nt][1][0];
            pr01 += v0 * w3r[nt][0][1] + v1 * w3r[nt][1][1];
            pr10 += v2 * w3r[nt][0][0] + v3 * w3r[nt][1][0];
            pr11 += v2 * w3r[nt][0][1] + v3 * w3r[nt][1][1];
        }
#pragma unroll
        for (int off = 1; off <= 2; off <<= 1) {
            pr00 += __shfl_xor_sync(0xffffffffu, pr00, off);
            pr01 += __shfl_xor_sync(0xffffffffu, pr01, off);
            pr10 += __shfl_xor_sync(0xffffffffu, pr10, off);
            pr11 += __shfl_xor_sync(0xffffffffu, pr11, off);
        }
        if (tc == 0) {
            int e0 = ebase + gr, e1 = ebase + gr + 8;
            if (e0 < E) *(float2*)&out[e0 * 2] = make_float2(pr00 + b30, pr01 + b31);
            if (e1 < E) *(float2*)&out[e1 * 2] = make_float2(pr10 + b30, pr11 + b31);
        }
        __syncwarp();
    }
}

// ---------------- host launcher ----------------
extern "C" void kernel_launch(void* const* d_in, const int* in_sizes, int n_in,
                              void* d_out, int out_size)
{
    const float* h     = (const float*)d_in[0];
    const int*   src   = (const int*)d_in[1];
    const int*   dst   = (const int*)d_in[2];
    const float* W_emb = (const float*)d_in[3];
    const float* b_emb = (const float*)d_in[4];
    const float* W_g   = (const float*)d_in[5];
    const float* al_g  = (const float*)d_in[6];
    const float* ar_g  = (const float*)d_in[7];
    const float* W_l   = (const float*)d_in[8];
    const float* al_l  = (const float*)d_in[9];
    const float* ar_l  = (const float*)d_in[10];
    const float* W1    = (const float*)d_in[11];
    const float* b1    = (const float*)d_in[12];
    const float* W2    = (const float*)d_in[13];
    const float* b2    = (const float*)d_in[14];
    const float* W3    = (const float*)d_in[15];
    const float* b3    = (const float*)d_in[16];
    float* out = (float*)d_out;

    int NN = in_sizes[0] / 128;
    int NE = in_sizes[1];

    float *x, *el, *er;
    __half *ft, *p, *q;
    int *deg, *cur, *rowstart, *csrc, *bsum, *boff;
    uint2* wpack;
    cudaGetSymbolAddress((void**)&x,   g_x);
    cudaGetSymbolAddress((void**)&ft,  g_ft);
    cudaGetSymbolAddress((void**)&el,  g_el);
    cudaGetSymbolAddress((void**)&er,  g_er);
    cudaGetSymbolAddress((void**)&p,   g_p);
    cudaGetSymbolAddress((void**)&q,   g_q);
    cudaGetSymbolAddress((void**)&deg, g_deg);
    cudaGetSymbolAddress((void**)&cur, g_cur);
    cudaGetSymbolAddress((void**)&rowstart, g_rowstart);
    cudaGetSymbolAddress((void**)&csrc, g_csrc);
    cudaGetSymbolAddress((void**)&bsum, g_bsum);
    cudaGetSymbolAddress((void**)&boff, g_boff);
    cudaGetSymbolAddress((void**)&wpack, g_wpack);

    const int FR = 8 * 16 * 32;   // uint2 per packed matrix

    // pack all 7 weight matrices (one launch)
    pack_w16_all<<<dim3(16, 7), 256>>>(W_emb, W_g, W_l, W1, wpack);

    // CSR build (by dst) — fully parallel
    int snb = (NN + 255) / 256;
    int et4 = (NE + 1023) / 1024;   // blocks of 256 threads, 4 edges each
    zero_int<<<(NN + 255) / 256, 256>>>(deg, NN);
    hist_dst<<<et4, 256>>>(dst, deg, NE);
    scan_p1<<<snb, 256>>>(deg, bsum, NN);
    scan_p2<<<1, 256>>>(bsum, boff, snb);
    scan_p3<<<snb, 256>>>(deg, boff, rowstart, cur, NN, NE);
    scatter_csr<<<et4, 256>>>(src, dst, cur, csrc, NE);

    int gemm_blocks = (NN + 63) / 64;

    // embedding (fp32 out, no attn)
    gemm_f16<0, 0, 0><<<gemm_blocks, 128>>>(h, wpack + 0 * FR, b_emb, x, nullptr, nullptr,
                                            nullptr, nullptr, nullptr, nullptr, NN);

    // 4 GAT layers
    for (int L = 0; L < 4; L++) {
        const uint2* Wp = wpack + (size_t)(L + 1) * FR;
        if (L < 3) {
            gemm_f16<8, 1, 0><<<gemm_blocks, 128>>>(x, Wp, nullptr, nullptr, (__half2*)ft,
                                                    nullptr, al_g + (size_t)L * 128,
                                                    ar_g + (size_t)L * 128, el, er, NN);
            gat_aggregate<<<(NN * 32 + 255) / 256, 256>>>(rowstart, csrc, ft, el, er, x,
                                                          8, 4, NN);
        } else {
            gemm_f16<1, 1, 0><<<gemm_blocks, 128>>>(x, Wp, nullptr, nullptr, (__half2*)ft,
                                                    nullptr, al_l, ar_l, el, er, NN);
            gat_aggregate<<<(NN * 32 + 255) / 256, 256>>>(rowstart, csrc, ft, el, er, x,
                                                          1, 7, NN);
        }
    }

    // p and q in ONE launch (grid.y selects half of W1)
    gemm_f16<0, 1, 1><<<dim3(gemm_blocks, 2), 128>>>(x, wpack + 5 * FR, nullptr, nullptr,
                                                     (__half2*)p, (__half2*)q,
                                                     nullptr, nullptr, nullptr, nullptr, NN);

    // fused edge MLP readout
    int ntiles = (NE + 15) / 16;
    size_t smem = 8 * 16 * 136 * sizeof(__half) + 8 * 8 * 32 * sizeof(uint2);
    cudaFuncSetAttribute(edge_mlp_tc, cudaFuncAttributeMaxDynamicSharedMemorySize,
                         (int)smem);
    edge_mlp_tc<<<1184, 256, smem>>>(src, dst, (const uint4*)p, (const uint4*)q,
                                     b1, W2, b2, W3, b3, out, NE, ntiles);
}